// round 9
// baseline (speedup 1.0000x reference)
#include <cuda_runtime.h>
#include <cuda_fp16.h>
#include <cstdint>

#define N_NODES 4096
#define MAXH 4

// ---------------- scratch (static device globals; no allocation) ----------------
__device__ unsigned g_maskw[N_NODES * 128];            // 2 MB adjacency bitmask
__device__ __half   g_h16T [MAXH * 64 * N_NODES];      // per-head features fp16, transposed [h][o][n]
__device__ float    g_el[MAXH * N_NODES], g_er[MAXH * N_NODES];
__device__ __half   g_Ph[MAXH * N_NODES], g_Qh[MAXH * N_NODES];
__device__ float    g_G1[MAXH * N_NODES], g_G2[MAXH * N_NODES];
__device__ float    g_buf0[N_NODES * 256];
__device__ float    g_buf1[N_NODES * 256];
__device__ float    g_part[16 * N_NODES * 68];         // split-m partials (SPLIT*H <= 16 slabs)

#define PACK2(d, lo, hi) asm("mov.b64 %0, {%1, %2};" : "=l"(d) : "f"(lo), "f"(hi))
#define UNPACK2(lo, hi, s) asm("mov.b64 {%0, %1}, %2;" : "=f"(lo), "=f"(hi) : "l"(s))
#define FMA2(acc, A, B) asm("fma.rn.f32x2 %0, %1, %2, %0;" : "+l"(acc) : "l"(A), "l"(B))

// ---------------- adjacency -> bitmask ----------------
__global__ void k_mask(const int* __restrict__ adj, unsigned* __restrict__ maskw) {
    int n = blockIdx.x;
    int tid = threadIdx.x;
    const int* row = adj + (size_t)n * N_NODES;
#pragma unroll
    for (int it = 0; it < 4; it++) {
        int m = it * 1024 + tid;
        unsigned b = __ballot_sync(0xffffffffu, row[m] > 0);
        if ((tid & 31) == 0) maskw[n * 128 + (m >> 5)] = b;
    }
}

// ---------------- feature GEMM + fused e_l/e_r epilogue ----------------
__global__ void k_feat(const float* __restrict__ in, const float* __restrict__ W,
                       const float* __restrict__ a,
                       __half* __restrict__ h16T,
                       float* __restrict__ el, float* __restrict__ er, int K) {
    __shared__ float Ast[16][68];   // k-major (transposed) for vector LDS
    __shared__ float Bs[16][68];
    const int h  = blockIdx.y;
    const int nb = blockIdx.x * 64;
    const int tid = threadIdx.x;
    const int tx = tid & 15, ty = tid >> 4;
    const float* Wh = W + (size_t)h * K * 64;

    unsigned long long acc2[4][2];
#pragma unroll
    for (int i = 0; i < 4; i++) { acc2[i][0] = 0ull; acc2[i][1] = 0ull; }

    for (int k0 = 0; k0 < K; k0 += 16) {
#pragma unroll
        for (int i = 0; i < 4; i++) {
            int idx = tid + i * 256;           // 0..1023
            int r = idx >> 4, c = idx & 15;
            Ast[c][r] = in[(size_t)(nb + r) * K + k0 + c];
        }
#pragma unroll
        for (int i = 0; i < 4; i++) {
            int idx = tid + i * 256;
            int r = idx >> 6, c = idx & 63;
            Bs[r][c] = Wh[(size_t)(k0 + r) * 64 + c];
        }
        __syncthreads();
#pragma unroll
        for (int kk = 0; kk < 16; kk++) {
            float4 a4 = *reinterpret_cast<const float4*>(&Ast[kk][ty * 4]);
            float4 b4 = *reinterpret_cast<const float4*>(&Bs[kk][tx * 4]);
            unsigned long long b01, b23, aa;
            PACK2(b01, b4.x, b4.y);
            PACK2(b23, b4.z, b4.w);
            PACK2(aa, a4.x, a4.x); FMA2(acc2[0][0], aa, b01); FMA2(acc2[0][1], aa, b23);
            PACK2(aa, a4.y, a4.y); FMA2(acc2[1][0], aa, b01); FMA2(acc2[1][1], aa, b23);
            PACK2(aa, a4.z, a4.z); FMA2(acc2[2][0], aa, b01); FMA2(acc2[2][1], aa, b23);
            PACK2(aa, a4.w, a4.w); FMA2(acc2[3][0], aa, b01); FMA2(acc2[3][1], aa, b23);
        }
        __syncthreads();
    }

    float acc[4][4];
#pragma unroll
    for (int i = 0; i < 4; i++) {
        UNPACK2(acc[i][0], acc[i][1], acc2[i][0]);
        UNPACK2(acc[i][2], acc[i][3], acc2[i][1]);
    }

    // fp16 transposed store
#pragma unroll
    for (int i = 0; i < 4; i++) {
        int n = nb + ty * 4 + i;
#pragma unroll
        for (int jj = 0; jj < 4; jj++)
            h16T[((size_t)h * 64 + tx * 4 + jj) * N_NODES + n] = __float2half_rn(acc[i][jj]);
    }

    // fused e_l/e_r: dot with a_l/a_r, reduce over the 16 lanes covering o
    float al[4], ar[4];
#pragma unroll
    for (int j = 0; j < 4; j++) {
        al[j] = a[h * 128 + tx * 4 + j];
        ar[j] = a[h * 128 + 64 + tx * 4 + j];
    }
#pragma unroll
    for (int i = 0; i < 4; i++) {
        float sl = 0.f, sr = 0.f;
#pragma unroll
        for (int j = 0; j < 4; j++) { sl = fmaf(acc[i][j], al[j], sl); sr = fmaf(acc[i][j], ar[j], sr); }
#pragma unroll
        for (int o = 1; o < 16; o <<= 1) {
            sl += __shfl_xor_sync(0xffffffffu, sl, o);
            sr += __shfl_xor_sync(0xffffffffu, sr, o);
        }
        if (tx == 0) {
            el[(size_t)h * N_NODES + nb + ty * 4 + i] = sl;
            er[(size_t)h * N_NODES + nb + ty * 4 + i] = sr;
        }
    }
}

// ---------------- fused per-head max + P,Q (half), G1,G2 (fp32) ----------------
__global__ void k_maxpqg(const float* __restrict__ el, const float* __restrict__ er,
                         float* __restrict__ G1, float* __restrict__ G2,
                         __half* __restrict__ Ph, __half* __restrict__ Qh) {
    const int h = blockIdx.x;
    const int base = h * N_NODES;
    __shared__ float sm[32];
    __shared__ float csh;
    float m = -3.4e38f;
    for (int i = threadIdx.x; i < N_NODES; i += 1024) m = fmaxf(m, er[base + i]);
#pragma unroll
    for (int o = 16; o; o >>= 1) m = fmaxf(m, __shfl_xor_sync(0xffffffffu, m, o));
    if ((threadIdx.x & 31) == 0) sm[threadIdx.x >> 5] = m;
    __syncthreads();
    if (threadIdx.x < 32) {
        float v = sm[threadIdx.x];
#pragma unroll
        for (int o = 16; o; o >>= 1) v = fmaxf(v, __shfl_xor_sync(0xffffffffu, v, o));
        if (threadIdx.x == 0) csh = v;
    }
    __syncthreads();
    const float c = csh;
    for (int i = threadIdx.x; i < N_NODES; i += 1024) {
        const float e_r = er[base + i], e_l = el[base + i];
        Ph[base + i] = __float2half_rn(expf(e_r - c));
        Qh[base + i] = __float2half_rn(expf(0.2f * (e_r - c)));
        const float z = e_l + c;
        if (z > 0.f) { G1[base + i] = 1.f;            G2[base + i] = expf(-0.8f * z); }
        else         { G1[base + i] = expf(0.8f * z); G2[base + i] = 1.f; }
    }
}

// ---------------- fused flash-style attention (split-m): partials = W @ h, rowsum ----------------
// W never touches smem: A-fragments are computed directly in mma lane layout.
struct AttnSmem {
    __half hTs[2][64 * 136];    // double-buffered h tiles (cp.async), hT[o][m]  34816 B
    __half Ppk[2048], Qpk[2048];// CTA's own m-range of P/Q                       8192 B
};

__device__ __forceinline__ unsigned smem_u32(const void* p) {
    return (unsigned)__cvta_generic_to_shared(p);
}
__device__ __forceinline__ __half2 u2h(unsigned u) { return *reinterpret_cast<__half2*>(&u); }
__device__ __forceinline__ unsigned h2u(__half2 h) { return *reinterpret_cast<unsigned*>(&h); }

#define CP_ASYNC16(dst_smem, src) \
    asm volatile("cp.async.cg.shared.global [%0], [%1], 16;" :: "r"(dst_smem), "l"(src))
#define CP_COMMIT() asm volatile("cp.async.commit_group;")
#define CP_WAIT0()  asm volatile("cp.async.wait_group 0;")

template<int SPLIT>
__global__ void __launch_bounds__(256, 3) k_attn(
    const __half* __restrict__ h16T,
    const __half* __restrict__ Phg, const __half* __restrict__ Qhg,
    const float* __restrict__ G1g, const float* __restrict__ G2g,
    const unsigned* __restrict__ maskw,
    float* __restrict__ part, int H) {
    extern __shared__ char smem_raw[];
    AttnSmem& S = *reinterpret_cast<AttnSmem*>(smem_raw);

    constexpr int NTILES = (N_NODES / 128) / SPLIT;
    const int head = blockIdx.y;
    const int n0   = blockIdx.x * 128;
    const int tid  = threadIdx.x;
    const int lane = tid & 31, warp = tid >> 5;
    const int tig  = lane & 3, gid = lane >> 2;
    const int t2   = tig * 2;
    const int rA   = warp * 16 + gid;          // this lane's two output rows
    const int rB   = rA + 8;
    const int hb   = head * N_NODES;
    const int jbase = blockIdx.z * NTILES;
    const int mbase = jbase * 128;

    // stage this CTA's m-range of packed P/Q
    {
        const uint4* Ps = reinterpret_cast<const uint4*>(Phg + hb + mbase);
        const uint4* Qs = reinterpret_cast<const uint4*>(Qhg + hb + mbase);
        uint4* Pd = reinterpret_cast<uint4*>(S.Ppk);
        uint4* Qd = reinterpret_cast<uint4*>(S.Qpk);
        constexpr int NV = NTILES * 16;   // uint4 count
#pragma unroll
        for (int i = tid; i < NV; i += 256) { Pd[i] = Ps[i]; Qd[i] = Qs[i]; }
    }
    const __half2 g1A = __float2half2_rn(G1g[hb + n0 + rA]);
    const __half2 g2A = __float2half2_rn(G2g[hb + n0 + rA]);
    const __half2 g1B = __float2half2_rn(G1g[hb + n0 + rB]);
    const __half2 g2B = __float2half2_rn(G2g[hb + n0 + rB]);

    float acc[8][4];
#pragma unroll
    for (int i = 0; i < 8; i++)
#pragma unroll
        for (int j = 0; j < 4; j++) acc[i][j] = 0.f;
    float acc_rs[4] = {0.f, 0.f, 0.f, 0.f};   // rowsum via ones-column MMA

    const __half* hT = h16T + (size_t)head * 64 * N_NODES;
    const unsigned* mrowA = maskw + (size_t)(n0 + rA) * 128;
    const unsigned* mrowB = maskw + (size_t)(n0 + rB) * 128;

    // cp.async load of h tile [64 o][128 m] into buffer
    auto load_tile = [&](int j, int buf) {
        const int m0 = j * 128;
#pragma unroll
        for (int i = 0; i < 4; i++) {
            int idx = tid + i * 256;
            int r = idx >> 4, c = idx & 15;
            unsigned dst = smem_u32(&S.hTs[buf][r * 136 + c * 8]);
            CP_ASYNC16(dst, hT + (size_t)r * N_NODES + m0 + c * 8);
        }
        CP_COMMIT();
    };

    load_tile(jbase, 0);
    // prefetch tile 0's adjacency words
    uint4 pAq = *reinterpret_cast<const uint4*>(mrowA + ((jbase * 128) >> 5));
    uint4 pBq = *reinterpret_cast<const uint4*>(mrowB + ((jbase * 128) >> 5));

#pragma unroll 1
    for (int t = 0; t < NTILES; t++) {
        const int m0 = (jbase + t) * 128;
        const int ml = m0 - mbase;
        const int buf = t & 1;

        CP_WAIT0();
        __syncthreads();                 // tile t visible to all; prior mma done
        if (t + 1 < NTILES) load_tile(jbase + t + 1, buf ^ 1);

        // current tile's mask words; prefetch next tile's
        const uint4 mAq = pAq, mBq = pBq;
        if (t + 1 < NTILES) {
            pAq = *reinterpret_cast<const uint4*>(mrowA + ((m0 + 128) >> 5));
            pBq = *reinterpret_cast<const uint4*>(mrowB + ((m0 + 128) >> 5));
        }
        // hoisted per-tile lane shift
        const unsigned vA[4] = {mAq.x >> t2, mAq.y >> t2, mAq.z >> t2, mAq.w >> t2};
        const unsigned vB[4] = {mBq.x >> t2, mBq.y >> t2, mBq.z >> t2, mBq.w >> t2};

        const unsigned bone = 0x3C003C00u;   // half2(1,1)
#pragma unroll
        for (int kc = 0; kc < 8; kc++) {
            // ---- A fragments in registers ----
            const unsigned sh = (kc & 1) * 16;
            const unsigned wA = vA[kc >> 1] >> sh;
            const unsigned wB = vB[kc >> 1] >> sh;
            const unsigned b01A = wA & 3u,  b89A = (wA >> 8) & 3u;
            const unsigned b01B = wB & 3u,  b89B = (wB >> 8) & 3u;
            const unsigned m01A = ((b01A & 1u) ? 0x0000FFFFu : 0u) | ((b01A & 2u) ? 0xFFFF0000u : 0u);
            const unsigned m89A = ((b89A & 1u) ? 0x0000FFFFu : 0u) | ((b89A & 2u) ? 0xFFFF0000u : 0u);
            const unsigned m01B = ((b01B & 1u) ? 0x0000FFFFu : 0u) | ((b01B & 2u) ? 0xFFFF0000u : 0u);
            const unsigned m89B = ((b89B & 1u) ? 0x0000FFFFu : 0u) | ((b89B & 2u) ? 0xFFFF0000u : 0u);

            const int mloc = ml + kc * 16 + t2;
            const __half2 Pp  = *reinterpret_cast<const __half2*>(S.Ppk + mloc);
            const __half2 Pp8 = *reinterpret_cast<const __half2*>(S.Ppk + mloc + 8);
            const __half2 Qp  = *reinterpret_cast<const __half2*>(S.Qpk + mloc);
            const __half2 Qp8 = *reinterpret_cast<const __half2*>(S.Qpk + mloc + 8);

            const unsigned a0 = h2u(__hmax2(__hmul2(g1A, Pp ), __hmul2(g2A, Qp ))) & m01A;
            const unsigned a1 = h2u(__hmax2(__hmul2(g1B, Pp ), __hmul2(g2B, Qp ))) & m01B;
            const unsigned a2 = h2u(__hmax2(__hmul2(g1A, Pp8), __hmul2(g2A, Qp8))) & m89A;
            const unsigned a3 = h2u(__hmax2(__hmul2(g1B, Pp8), __hmul2(g2B, Qp8))) & m89B;

            // rowsum via ones-B MMA
            asm volatile(
                "mma.sync.aligned.m16n8k16.row.col.f32.f16.f16.f32 "
                "{%0,%1,%2,%3}, {%4,%5,%6,%7}, {%8,%9}, {%0,%1,%2,%3};\n"
                : "+f"(acc_rs[0]), "+f"(acc_rs[1]), "+f"(acc_rs[2]), "+f"(acc_rs[3])
                : "r"(a0), "r"(a1), "r"(a2), "r"(a3), "r"(bone), "r"(bone));
#pragma unroll
            for (int ncp = 0; ncp < 4; ncp++) {
                int g = lane >> 3, r = lane & 7;
                int brw  = ncp * 16 + (g >> 1) * 8 + r;
                int bcol = kc * 16 + (g & 1) * 8;
                unsigned baddr = smem_u32(&S.hTs[buf][brw * 136 + bcol]);
                unsigned b0, b1, b2, b3;
                asm volatile("ldmatrix.sync.aligned.m8n8.x4.shared.b16 {%0,%1,%2,%3}, [%4];\n"
                             : "=r"(b0), "=r"(b1), "=r"(b2), "=r"(b3) : "r"(baddr));
                asm volatile(
                    "mma.sync.aligned.m16n8k16.row.col.f32.f16.f16.f32 "
                    "{%0,%1,%2,%3}, {%4,%5,%6,%7}, {%8,%9}, {%0,%1,%2,%3};\n"
                    : "+f"(acc[2 * ncp][0]), "+f"(acc[2 * ncp][1]),
                      "+f"(acc[2 * ncp][2]), "+f"(acc[2 * ncp][3])
                    : "r"(a0), "r"(a1), "r"(a2), "r"(a3), "r"(b0), "r"(b1));
                asm volatile(
                    "mma.sync.aligned.m16n8k16.row.col.f32.f16.f16.f32 "
                    "{%0,%1,%2,%3}, {%4,%5,%6,%7}, {%8,%9}, {%0,%1,%2,%3};\n"
                    : "+f"(acc[2 * ncp + 1][0]), "+f"(acc[2 * ncp + 1][1]),
                      "+f"(acc[2 * ncp + 1][2]), "+f"(acc[2 * ncp + 1][3])
                    : "r"(a0), "r"(a1), "r"(a2), "r"(a3), "r"(b2), "r"(b3));
            }
        }
    }

    // ---- write partial (numerator + rowsum) ----
    float* pbase = part + (((size_t)blockIdx.z * H + head) * N_NODES + n0) * 68;
#pragma unroll
    for (int nc = 0; nc < 8; nc++) {
        int col = nc * 8 + t2;
        *reinterpret_cast<float2*>(pbase + (size_t)rA * 68 + col) = make_float2(acc[nc][0], acc[nc][1]);
        *reinterpret_cast<float2*>(pbase + (size_t)rB * 68 + col) = make_float2(acc[nc][2], acc[nc][3]);
    }
    if (tig == 0) {
        pbase[(size_t)rA * 68 + 64] = acc_rs[0];
        pbase[(size_t)rB * 68 + 64] = acc_rs[2];
    }
}

// ---------------- combine split-m partials: divide + optional ELU ----------------
__global__ void k_combine(const float* __restrict__ part, float* __restrict__ out,
                          int H, int SPLIT, int outStride, int applyElu) {
    const int idx = blockIdx.x * 256 + threadIdx.x;    // over H*N*64
    const int o = idx & 63, n = (idx >> 6) & (N_NODES - 1), head = idx >> 18;
    float s = 0.f, r = 0.f;
    for (int z = 0; z < SPLIT; z++) {
        const float* pb = part + (((size_t)z * H + head) * N_NODES + n) * 68;
        s += pb[o];
        r += pb[64];
    }
    float v = s / r;
    if (applyElu) v = v > 0.f ? v : expm1f(v);
    out[(size_t)n * outStride + head * 64 + o] = v;
}

// ---------------- host orchestration ----------------
struct Scratch {
    unsigned* maskw; __half* h16T;
    float *el, *er, *G1, *G2, *buf0, *buf1, *part;
    __half *Ph, *Qh;
};

static void run_layer(const float* in, int K, const float* W, const float* a, int H,
                      float* outp, int outStride, int applyElu, const Scratch& s) {
    k_feat<<<dim3(64, H), 256>>>(in, W, a, s.h16T, s.el, s.er, K);
    k_maxpqg<<<H, 1024>>>(s.el, s.er, s.G1, s.G2, s.Ph, s.Qh);
    if (H == 4) {
        // 256 CTAs = exactly one co-residency wave at 3 CTAs/SM
        k_attn<2><<<dim3(N_NODES / 128, H, 2), 256, sizeof(AttnSmem)>>>(
            s.h16T, s.Ph, s.Qh, s.G1, s.G2, s.maskw, s.part, H);
        k_combine<<<H * N_NODES * 64 / 256, 256>>>(s.part, outp, H, 2, outStride, applyElu);
    } else {
        k_attn<8><<<dim3(N_NODES / 128, H, 8), 256, sizeof(AttnSmem)>>>(
            s.h16T, s.Ph, s.Qh, s.G1, s.G2, s.maskw, s.part, H);
        k_combine<<<H * N_NODES * 64 / 256, 256>>>(s.part, outp, H, 8, outStride, applyElu);
    }
}

extern "C" void kernel_launch(void* const* d_in, const int* in_sizes, int n_in,
                              void* d_out, int out_size) {
    (void)in_sizes; (void)n_in; (void)out_size;
    const float* x  = (const float*)d_in[0];
    const int*   adj = (const int*)d_in[1];
    const float* W0 = (const float*)d_in[2];
    const float* a0 = (const float*)d_in[3];
    const float* W1 = (const float*)d_in[4];
    const float* a1 = (const float*)d_in[5];
    const float* W2 = (const float*)d_in[6];
    const float* a2 = (const float*)d_in[7];

    cudaFuncSetAttribute(k_attn<2>, cudaFuncAttributeMaxDynamicSharedMemorySize,
                         (int)sizeof(AttnSmem));
    cudaFuncSetAttribute(k_attn<8>, cudaFuncAttributeMaxDynamicSharedMemorySize,
                         (int)sizeof(AttnSmem));

    Scratch s;
    void* p;
    cudaGetSymbolAddress(&p, g_maskw); s.maskw = (unsigned*)p;
    cudaGetSymbolAddress(&p, g_h16T);  s.h16T  = (__half*)p;
    cudaGetSymbolAddress(&p, g_el);    s.el    = (float*)p;
    cudaGetSymbolAddress(&p, g_er);    s.er    = (float*)p;
    cudaGetSymbolAddress(&p, g_G1);    s.G1    = (float*)p;
    cudaGetSymbolAddress(&p, g_G2);    s.G2    = (float*)p;
    cudaGetSymbolAddress(&p, g_buf0);  s.buf0  = (float*)p;
    cudaGetSymbolAddress(&p, g_buf1);  s.buf1  = (float*)p;
    cudaGetSymbolAddress(&p, g_part);  s.part  = (float*)p;
    cudaGetSymbolAddress(&p, g_Ph);    s.Ph    = (__half*)p;
    cudaGetSymbolAddress(&p, g_Qh);    s.Qh    = (__half*)p;

    k_mask<<<N_NODES, 1024>>>(adj, s.maskw);

    run_layer(x,      128, W0, a0, 4, s.buf0,        256, 1, s);
    run_layer(s.buf0, 256, W1, a1, 4, s.buf1,        256, 1, s);
    run_layer(s.buf1, 256, W2, a2, 1, (float*)d_out,  64, 0, s);
}

// round 10
// speedup vs baseline: 1.1563x; 1.1563x over previous
#include <cuda_runtime.h>
#include <cuda_fp16.h>
#include <cstdint>

#define N_NODES 4096
#define MAXH 4

// ---------------- scratch (static device globals; no allocation) ----------------
__device__ unsigned g_maskw[N_NODES * 128];            // 2 MB adjacency bitmask
__device__ __half   g_h16T [MAXH * 64 * N_NODES];      // per-head features fp16, transposed [h][o][n]
__device__ float    g_el[MAXH * N_NODES], g_er[MAXH * N_NODES];
__device__ __half   g_Ph[MAXH * N_NODES], g_Qh[MAXH * N_NODES];
__device__ float    g_G1[MAXH * N_NODES], g_G2[MAXH * N_NODES];
__device__ __half   g_x16 [N_NODES * 128];             // layer-0 input, fp16
__device__ __half   g_bufA[N_NODES * 256];             // layer-0 output, fp16
__device__ __half   g_bufB[N_NODES * 256];             // layer-1 output, fp16
__device__ float    g_part[16 * N_NODES * 68];         // split-m partials (SPLIT*H <= 16 slabs)

// ---------------- adjacency -> bitmask ----------------
__global__ void k_mask(const int* __restrict__ adj, unsigned* __restrict__ maskw) {
    int n = blockIdx.x;
    int tid = threadIdx.x;
    const int* row = adj + (size_t)n * N_NODES;
#pragma unroll
    for (int it = 0; it < 4; it++) {
        int m = it * 1024 + tid;
        unsigned b = __ballot_sync(0xffffffffu, row[m] > 0);
        if ((tid & 31) == 0) maskw[n * 128 + (m >> 5)] = b;
    }
}

// ---------------- x fp32 -> fp16 ----------------
__global__ void k_x2h(const float* __restrict__ in, __half* __restrict__ out, int n4) {
    int i = blockIdx.x * 256 + threadIdx.x;
    if (i < n4) {
        float4 f = reinterpret_cast<const float4*>(in)[i];
        __half2 lo = __floats2half2_rn(f.x, f.y);
        __half2 hi = __floats2half2_rn(f.z, f.w);
        reinterpret_cast<uint2*>(out)[i] =
            make_uint2(*reinterpret_cast<unsigned*>(&lo), *reinterpret_cast<unsigned*>(&hi));
    }
}

__device__ __forceinline__ unsigned smem_u32(const void* p) {
    return (unsigned)__cvta_generic_to_shared(p);
}
__device__ __forceinline__ __half2 u2h(unsigned u) { return *reinterpret_cast<__half2*>(&u); }
__device__ __forceinline__ unsigned h2u(__half2 h) { return *reinterpret_cast<unsigned*>(&h); }

// ---------------- tensor-core feature GEMM + fused e_l/e_r ----------------
// h[n][o] = in16[n][:K] @ W[h][:K][o]  (fp16 x fp16 -> fp32), writes h16T + el/er
template<int K>
__global__ void __launch_bounds__(256) k_feat_tc(
    const __half* __restrict__ in16, const float* __restrict__ W,
    const float* __restrict__ a,
    __half* __restrict__ h16T, float* __restrict__ el, float* __restrict__ er) {
    __shared__ __half As[128 * 72];    // [row][k] padded
    __shared__ __half WT[64 * 72];     // [o][k]  padded
    const int h  = blockIdx.y;
    const int nb = blockIdx.x * 128;
    const int tid = threadIdx.x;
    const int lane = tid & 31, warp = tid >> 5;
    const int tig = lane & 3, gid = lane >> 2;
    const float* Wh = W + (size_t)h * K * 64;

    float acc[8][4];
#pragma unroll
    for (int i = 0; i < 8; i++)
#pragma unroll
        for (int j = 0; j < 4; j++) acc[i][j] = 0.f;

    const int arow = warp * 16 + (lane & 15);
    const unsigned aaddr = smem_u32(&As[arow * 72 + (lane >> 4) * 8]);

#pragma unroll 1
    for (int k0 = 0; k0 < K; k0 += 64) {
        __syncthreads();
        // A tile: 128 rows x 64 k halfs
#pragma unroll
        for (int i = 0; i < 4; i++) {
            int idx = tid + i * 256;       // 0..1023
            int r = idx >> 3, c = idx & 7;
            *reinterpret_cast<uint4*>(&As[r * 72 + c * 8]) =
                *reinterpret_cast<const uint4*>(in16 + (size_t)(nb + r) * K + k0 + c * 8);
        }
        // W tile: 64 k x 64 o fp32 -> WT[o][k] fp16
#pragma unroll
        for (int i = 0; i < 4; i++) {
            int idx = tid + i * 256;
            int kk = idx >> 4, og = (idx & 15) * 4;
            float4 w4 = *reinterpret_cast<const float4*>(&Wh[(size_t)(k0 + kk) * 64 + og]);
            WT[(og + 0) * 72 + kk] = __float2half_rn(w4.x);
            WT[(og + 1) * 72 + kk] = __float2half_rn(w4.y);
            WT[(og + 2) * 72 + kk] = __float2half_rn(w4.z);
            WT[(og + 3) * 72 + kk] = __float2half_rn(w4.w);
        }
        __syncthreads();
#pragma unroll
        for (int kc = 0; kc < 4; kc++) {
            unsigned a0, a1, a2, a3;
            asm volatile("ldmatrix.sync.aligned.m8n8.x4.shared.b16 {%0,%1,%2,%3}, [%4];\n"
                         : "=r"(a0), "=r"(a1), "=r"(a2), "=r"(a3)
                         : "r"(aaddr + kc * 32));
#pragma unroll
            for (int ncp = 0; ncp < 4; ncp++) {
                int g = lane >> 3, r = lane & 7;
                int brw  = ncp * 16 + (g >> 1) * 8 + r;
                int bcol = kc * 16 + (g & 1) * 8;
                unsigned baddr = smem_u32(&WT[brw * 72 + bcol]);
                unsigned b0, b1, b2, b3;
                asm volatile("ldmatrix.sync.aligned.m8n8.x4.shared.b16 {%0,%1,%2,%3}, [%4];\n"
                             : "=r"(b0), "=r"(b1), "=r"(b2), "=r"(b3) : "r"(baddr));
                asm volatile(
                    "mma.sync.aligned.m16n8k16.row.col.f32.f16.f16.f32 "
                    "{%0,%1,%2,%3}, {%4,%5,%6,%7}, {%8,%9}, {%0,%1,%2,%3};\n"
                    : "+f"(acc[2 * ncp][0]), "+f"(acc[2 * ncp][1]),
                      "+f"(acc[2 * ncp][2]), "+f"(acc[2 * ncp][3])
                    : "r"(a0), "r"(a1), "r"(a2), "r"(a3), "r"(b0), "r"(b1));
                asm volatile(
                    "mma.sync.aligned.m16n8k16.row.col.f32.f16.f16.f32 "
                    "{%0,%1,%2,%3}, {%4,%5,%6,%7}, {%8,%9}, {%0,%1,%2,%3};\n"
                    : "+f"(acc[2 * ncp + 1][0]), "+f"(acc[2 * ncp + 1][1]),
                      "+f"(acc[2 * ncp + 1][2]), "+f"(acc[2 * ncp + 1][3])
                    : "r"(a0), "r"(a1), "r"(a2), "r"(a3), "r"(b2), "r"(b3));
            }
        }
    }

    // ---- epilogue: h16T stores + el/er from fp32 accumulators ----
    const int n_lo = nb + warp * 16 + gid;
    const int n_hi = n_lo + 8;
    const int hb = h * N_NODES;
    __half* hTb = h16T + ((size_t)h * 64) * N_NODES;
    const float* ah = a + h * 128;

    float pl0 = 0.f, pl1 = 0.f, pr0 = 0.f, pr1 = 0.f;
#pragma unroll
    for (int nc = 0; nc < 8; nc++) {
        const int c0 = nc * 8 + 2 * tig;
        hTb[(size_t)c0 * N_NODES + n_lo]       = __float2half_rn(acc[nc][0]);
        hTb[(size_t)(c0 + 1) * N_NODES + n_lo] = __float2half_rn(acc[nc][1]);
        hTb[(size_t)c0 * N_NODES + n_hi]       = __float2half_rn(acc[nc][2]);
        hTb[(size_t)(c0 + 1) * N_NODES + n_hi] = __float2half_rn(acc[nc][3]);
        const float al0 = ah[c0], al1 = ah[c0 + 1];
        const float ar0 = ah[64 + c0], ar1 = ah[64 + c0 + 1];
        pl0 = fmaf(acc[nc][0], al0, fmaf(acc[nc][1], al1, pl0));
        pl1 = fmaf(acc[nc][2], al0, fmaf(acc[nc][3], al1, pl1));
        pr0 = fmaf(acc[nc][0], ar0, fmaf(acc[nc][1], ar1, pr0));
        pr1 = fmaf(acc[nc][2], ar0, fmaf(acc[nc][3], ar1, pr1));
    }
#pragma unroll
    for (int o = 1; o < 4; o <<= 1) {
        pl0 += __shfl_xor_sync(0xffffffffu, pl0, o);
        pl1 += __shfl_xor_sync(0xffffffffu, pl1, o);
        pr0 += __shfl_xor_sync(0xffffffffu, pr0, o);
        pr1 += __shfl_xor_sync(0xffffffffu, pr1, o);
    }
    if (tig == 0) {
        el[hb + n_lo] = pl0; el[hb + n_hi] = pl1;
        er[hb + n_lo] = pr0; er[hb + n_hi] = pr1;
    }
}

// ---------------- fused per-head max + P,Q (half), G1,G2 (fp32) ----------------
__global__ void k_maxpqg(const float* __restrict__ el, const float* __restrict__ er,
                         float* __restrict__ G1, float* __restrict__ G2,
                         __half* __restrict__ Ph, __half* __restrict__ Qh) {
    const int h = blockIdx.x;
    const int base = h * N_NODES;
    __shared__ float sm[32];
    __shared__ float csh;
    float m = -3.4e38f;
    for (int i = threadIdx.x; i < N_NODES; i += 1024) m = fmaxf(m, er[base + i]);
#pragma unroll
    for (int o = 16; o; o >>= 1) m = fmaxf(m, __shfl_xor_sync(0xffffffffu, m, o));
    if ((threadIdx.x & 31) == 0) sm[threadIdx.x >> 5] = m;
    __syncthreads();
    if (threadIdx.x < 32) {
        float v = sm[threadIdx.x];
#pragma unroll
        for (int o = 16; o; o >>= 1) v = fmaxf(v, __shfl_xor_sync(0xffffffffu, v, o));
        if (threadIdx.x == 0) csh = v;
    }
    __syncthreads();
    const float c = csh;
    for (int i = threadIdx.x; i < N_NODES; i += 1024) {
        const float e_r = er[base + i], e_l = el[base + i];
        Ph[base + i] = __float2half_rn(expf(e_r - c));
        Qh[base + i] = __float2half_rn(expf(0.2f * (e_r - c)));
        const float z = e_l + c;
        if (z > 0.f) { G1[base + i] = 1.f;            G2[base + i] = expf(-0.8f * z); }
        else         { G1[base + i] = expf(0.8f * z); G2[base + i] = 1.f; }
    }
}

// ---------------- fused flash-style attention (split-m): partials = W @ h, rowsum ----------------
struct AttnSmem {
    __half hTs[2][64 * 136];    // double-buffered h tiles (cp.async), hT[o][m]  34816 B
    __half Ppk[2048], Qpk[2048];// CTA's own m-range of P/Q                       8192 B
};

#define CP_ASYNC16(dst_smem, src) \
    asm volatile("cp.async.cg.shared.global [%0], [%1], 16;" :: "r"(dst_smem), "l"(src))
#define CP_COMMIT() asm volatile("cp.async.commit_group;")
#define CP_WAIT0()  asm volatile("cp.async.wait_group 0;")

template<int SPLIT>
__global__ void __launch_bounds__(256, 3) k_attn(
    const __half* __restrict__ h16T,
    const __half* __restrict__ Phg, const __half* __restrict__ Qhg,
    const float* __restrict__ G1g, const float* __restrict__ G2g,
    const unsigned* __restrict__ maskw,
    float* __restrict__ part, int H) {
    extern __shared__ char smem_raw[];
    AttnSmem& S = *reinterpret_cast<AttnSmem*>(smem_raw);

    constexpr int NTILES = (N_NODES / 128) / SPLIT;
    const int head = blockIdx.y;
    const int n0   = blockIdx.x * 128;
    const int tid  = threadIdx.x;
    const int lane = tid & 31, warp = tid >> 5;
    const int tig  = lane & 3, gid = lane >> 2;
    const int t2   = tig * 2;
    const int rA   = warp * 16 + gid;
    const int rB   = rA + 8;
    const int hb   = head * N_NODES;
    const int jbase = blockIdx.z * NTILES;
    const int mbase = jbase * 128;

    {
        const uint4* Ps = reinterpret_cast<const uint4*>(Phg + hb + mbase);
        const uint4* Qs = reinterpret_cast<const uint4*>(Qhg + hb + mbase);
        uint4* Pd = reinterpret_cast<uint4*>(S.Ppk);
        uint4* Qd = reinterpret_cast<uint4*>(S.Qpk);
        constexpr int NV = NTILES * 16;
#pragma unroll
        for (int i = tid; i < NV; i += 256) { Pd[i] = Ps[i]; Qd[i] = Qs[i]; }
    }
    const __half2 g1A = __float2half2_rn(G1g[hb + n0 + rA]);
    const __half2 g2A = __float2half2_rn(G2g[hb + n0 + rA]);
    const __half2 g1B = __float2half2_rn(G1g[hb + n0 + rB]);
    const __half2 g2B = __float2half2_rn(G2g[hb + n0 + rB]);

    float acc[8][4];
#pragma unroll
    for (int i = 0; i < 8; i++)
#pragma unroll
        for (int j = 0; j < 4; j++) acc[i][j] = 0.f;
    float acc_rs[4] = {0.f, 0.f, 0.f, 0.f};

    const __half* hT = h16T + (size_t)head * 64 * N_NODES;
    const unsigned* mrowA = maskw + (size_t)(n0 + rA) * 128;
    const unsigned* mrowB = maskw + (size_t)(n0 + rB) * 128;

    auto load_tile = [&](int j, int buf) {
        const int m0 = j * 128;
#pragma unroll
        for (int i = 0; i < 4; i++) {
            int idx = tid + i * 256;
            int r = idx >> 4, c = idx & 15;
            unsigned dst = smem_u32(&S.hTs[buf][r * 136 + c * 8]);
            CP_ASYNC16(dst, hT + (size_t)r * N_NODES + m0 + c * 8);
        }
        CP_COMMIT();
    };

    load_tile(jbase, 0);
    uint4 pAq = *reinterpret_cast<const uint4*>(mrowA + ((jbase * 128) >> 5));
    uint4 pBq = *reinterpret_cast<const uint4*>(mrowB + ((jbase * 128) >> 5));

#pragma unroll 1
    for (int t = 0; t < NTILES; t++) {
        const int m0 = (jbase + t) * 128;
        const int ml = m0 - mbase;
        const int buf = t & 1;

        CP_WAIT0();
        __syncthreads();
        if (t + 1 < NTILES) load_tile(jbase + t + 1, buf ^ 1);

        const uint4 mAq = pAq, mBq = pBq;
        if (t + 1 < NTILES) {
            pAq = *reinterpret_cast<const uint4*>(mrowA + ((m0 + 128) >> 5));
            pBq = *reinterpret_cast<const uint4*>(mrowB + ((m0 + 128) >> 5));
        }
        const unsigned vA[4] = {mAq.x >> t2, mAq.y >> t2, mAq.z >> t2, mAq.w >> t2};
        const unsigned vB[4] = {mBq.x >> t2, mBq.y >> t2, mBq.z >> t2, mBq.w >> t2};

        const unsigned bone = 0x3C003C00u;
#pragma unroll
        for (int kc = 0; kc < 8; kc++) {
            const unsigned sh = (kc & 1) * 16;
            const unsigned wA = vA[kc >> 1] >> sh;
            const unsigned wB = vB[kc >> 1] >> sh;
            const unsigned b01A = wA & 3u,  b89A = (wA >> 8) & 3u;
            const unsigned b01B = wB & 3u,  b89B = (wB >> 8) & 3u;
            const unsigned m01A = ((b01A & 1u) ? 0x0000FFFFu : 0u) | ((b01A & 2u) ? 0xFFFF0000u : 0u);
            const unsigned m89A = ((b89A & 1u) ? 0x0000FFFFu : 0u) | ((b89A & 2u) ? 0xFFFF0000u : 0u);
            const unsigned m01B = ((b01B & 1u) ? 0x0000FFFFu : 0u) | ((b01B & 2u) ? 0xFFFF0000u : 0u);
            const unsigned m89B = ((b89B & 1u) ? 0x0000FFFFu : 0u) | ((b89B & 2u) ? 0xFFFF0000u : 0u);

            const int mloc = ml + kc * 16 + t2;
            const __half2 Pp  = *reinterpret_cast<const __half2*>(S.Ppk + mloc);
            const __half2 Pp8 = *reinterpret_cast<const __half2*>(S.Ppk + mloc + 8);
            const __half2 Qp  = *reinterpret_cast<const __half2*>(S.Qpk + mloc);
            const __half2 Qp8 = *reinterpret_cast<const __half2*>(S.Qpk + mloc + 8);

            const unsigned a0 = h2u(__hmax2(__hmul2(g1A, Pp ), __hmul2(g2A, Qp ))) & m01A;
            const unsigned a1 = h2u(__hmax2(__hmul2(g1B, Pp ), __hmul2(g2B, Qp ))) & m01B;
            const unsigned a2 = h2u(__hmax2(__hmul2(g1A, Pp8), __hmul2(g2A, Qp8))) & m89A;
            const unsigned a3 = h2u(__hmax2(__hmul2(g1B, Pp8), __hmul2(g2B, Qp8))) & m89B;

            asm volatile(
                "mma.sync.aligned.m16n8k16.row.col.f32.f16.f16.f32 "
                "{%0,%1,%2,%3}, {%4,%5,%6,%7}, {%8,%9}, {%0,%1,%2,%3};\n"
                : "+f"(acc_rs[0]), "+f"(acc_rs[1]), "+f"(acc_rs[2]), "+f"(acc_rs[3])
                : "r"(a0), "r"(a1), "r"(a2), "r"(a3), "r"(bone), "r"(bone));
#pragma unroll
            for (int ncp = 0; ncp < 4; ncp++) {
                int g = lane >> 3, r = lane & 7;
                int brw  = ncp * 16 + (g >> 1) * 8 + r;
                int bcol = kc * 16 + (g & 1) * 8;
                unsigned baddr = smem_u32(&S.hTs[buf][brw * 136 + bcol]);
                unsigned b0, b1, b2, b3;
                asm volatile("ldmatrix.sync.aligned.m8n8.x4.shared.b16 {%0,%1,%2,%3}, [%4];\n"
                             : "=r"(b0), "=r"(b1), "=r"(b2), "=r"(b3) : "r"(baddr));
                asm volatile(
                    "mma.sync.aligned.m16n8k16.row.col.f32.f16.f16.f32 "
                    "{%0,%1,%2,%3}, {%4,%5,%6,%7}, {%8,%9}, {%0,%1,%2,%3};\n"
                    : "+f"(acc[2 * ncp][0]), "+f"(acc[2 * ncp][1]),
                      "+f"(acc[2 * ncp][2]), "+f"(acc[2 * ncp][3])
                    : "r"(a0), "r"(a1), "r"(a2), "r"(a3), "r"(b0), "r"(b1));
                asm volatile(
                    "mma.sync.aligned.m16n8k16.row.col.f32.f16.f16.f32 "
                    "{%0,%1,%2,%3}, {%4,%5,%6,%7}, {%8,%9}, {%0,%1,%2,%3};\n"
                    : "+f"(acc[2 * ncp + 1][0]), "+f"(acc[2 * ncp + 1][1]),
                      "+f"(acc[2 * ncp + 1][2]), "+f"(acc[2 * ncp + 1][3])
                    : "r"(a0), "r"(a1), "r"(a2), "r"(a3), "r"(b2), "r"(b3));
            }
        }
    }

    float* pbase = part + (((size_t)blockIdx.z * H + head) * N_NODES + n0) * 68;
#pragma unroll
    for (int nc = 0; nc < 8; nc++) {
        int col = nc * 8 + t2;
        *reinterpret_cast<float2*>(pbase + (size_t)rA * 68 + col) = make_float2(acc[nc][0], acc[nc][1]);
        *reinterpret_cast<float2*>(pbase + (size_t)rB * 68 + col) = make_float2(acc[nc][2], acc[nc][3]);
    }
    if (tig == 0) {
        pbase[(size_t)rA * 68 + 64] = acc_rs[0];
        pbase[(size_t)rB * 68 + 64] = acc_rs[2];
    }
}

// ---------------- combine split-m partials: divide + optional ELU; fp16 or fp32 out ----------------
template<bool HALF_OUT>
__global__ void k_combine(const float* __restrict__ part, float* __restrict__ fout,
                          __half* __restrict__ hout,
                          int H, int SPLIT, int outStride, int applyElu) {
    const int idx = blockIdx.x * 256 + threadIdx.x;    // over H*N*64
    const int o = idx & 63, n = (idx >> 6) & (N_NODES - 1), head = idx >> 18;
    float s = 0.f, r = 0.f;
    for (int z = 0; z < SPLIT; z++) {
        const float* pb = part + (((size_t)z * H + head) * N_NODES + n) * 68;
        s += pb[o];
        r += pb[64];
    }
    float v = s / r;
    if (applyElu) v = v > 0.f ? v : expm1f(v);
    if (HALF_OUT) hout[(size_t)n * outStride + head * 64 + o] = __float2half_rn(v);
    else          fout[(size_t)n * outStride + head * 64 + o] = v;
}

// ---------------- host orchestration ----------------
struct Scratch {
    unsigned* maskw; __half* h16T;
    float *el, *er, *G1, *G2, *part;
    __half *Ph, *Qh, *x16, *bufA, *bufB;
};

static void run_layer(const __half* in16, int K, const float* W, const float* a, int H,
                      float* foutp, __half* houtp, int outStride, int applyElu,
                      const Scratch& s) {
    if (K == 128) k_feat_tc<128><<<dim3(N_NODES / 128, H), 256>>>(in16, W, a, s.h16T, s.el, s.er);
    else          k_feat_tc<256><<<dim3(N_NODES / 128, H), 256>>>(in16, W, a, s.h16T, s.el, s.er);
    k_maxpqg<<<H, 1024>>>(s.el, s.er, s.G1, s.G2, s.Ph, s.Qh);
    if (H == 4) {
        k_attn<4><<<dim3(N_NODES / 128, H, 4), 256, sizeof(AttnSmem)>>>(
            s.h16T, s.Ph, s.Qh, s.G1, s.G2, s.maskw, s.part, H);
        if (houtp) k_combine<true ><<<H * N_NODES * 64 / 256, 256>>>(s.part, foutp, houtp, H, 4, outStride, applyElu);
        else       k_combine<false><<<H * N_NODES * 64 / 256, 256>>>(s.part, foutp, houtp, H, 4, outStride, applyElu);
    } else {
        k_attn<8><<<dim3(N_NODES / 128, H, 8), 256, sizeof(AttnSmem)>>>(
            s.h16T, s.Ph, s.Qh, s.G1, s.G2, s.maskw, s.part, H);
        if (houtp) k_combine<true ><<<H * N_NODES * 64 / 256, 256>>>(s.part, foutp, houtp, H, 8, outStride, applyElu);
        else       k_combine<false><<<H * N_NODES * 64 / 256, 256>>>(s.part, foutp, houtp, H, 8, outStride, applyElu);
    }
}

extern "C" void kernel_launch(void* const* d_in, const int* in_sizes, int n_in,
                              void* d_out, int out_size) {
    (void)in_sizes; (void)n_in; (void)out_size;
    const float* x  = (const float*)d_in[0];
    const int*   adj = (const int*)d_in[1];
    const float* W0 = (const float*)d_in[2];
    const float* a0 = (const float*)d_in[3];
    const float* W1 = (const float*)d_in[4];
    const float* a1 = (const float*)d_in[5];
    const float* W2 = (const float*)d_in[6];
    const float* a2 = (const float*)d_in[7];

    cudaFuncSetAttribute(k_attn<4>, cudaFuncAttributeMaxDynamicSharedMemorySize,
                         (int)sizeof(AttnSmem));
    cudaFuncSetAttribute(k_attn<8>, cudaFuncAttributeMaxDynamicSharedMemorySize,
                         (int)sizeof(AttnSmem));

    Scratch s;
    void* p;
    cudaGetSymbolAddress(&p, g_maskw); s.maskw = (unsigned*)p;
    cudaGetSymbolAddress(&p, g_h16T);  s.h16T  = (__half*)p;
    cudaGetSymbolAddress(&p, g_el);    s.el    = (float*)p;
    cudaGetSymbolAddress(&p, g_er);    s.er    = (float*)p;
    cudaGetSymbolAddress(&p, g_G1);    s.G1    = (float*)p;
    cudaGetSymbolAddress(&p, g_G2);    s.G2    = (float*)p;
    cudaGetSymbolAddress(&p, g_part);  s.part  = (float*)p;
    cudaGetSymbolAddress(&p, g_Ph);    s.Ph    = (__half*)p;
    cudaGetSymbolAddress(&p, g_Qh);    s.Qh    = (__half*)p;
    cudaGetSymbolAddress(&p, g_x16);   s.x16   = (__half*)p;
    cudaGetSymbolAddress(&p, g_bufA);  s.bufA  = (__half*)p;
    cudaGetSymbolAddress(&p, g_bufB);  s.bufB  = (__half*)p;

    k_mask<<<N_NODES, 1024>>>(adj, s.maskw);
    k_x2h<<<(N_NODES * 128 / 4 + 255) / 256, 256>>>(x, s.x16, N_NODES * 128 / 4);

    run_layer(s.x16,  128, W0, a0, 4, nullptr,        s.bufA, 256, 1, s);
    run_layer(s.bufA, 256, W1, a1, 4, nullptr,        s.bufB, 256, 1, s);
    run_layer(s.bufB, 256, W2, a2, 1, (float*)d_out,  nullptr, 64, 0, s);
}

// round 11
// speedup vs baseline: 1.2151x; 1.0509x over previous
#include <cuda_runtime.h>
#include <cuda_fp16.h>
#include <cstdint>

#define N_NODES 4096
#define MAXH 4

// ---------------- scratch (static device globals; no allocation) ----------------
__device__ unsigned g_maskw[N_NODES * 128];            // 2 MB adjacency bitmask
__device__ __half   g_h16T [MAXH * 64 * N_NODES];      // per-head features fp16, transposed [h][o][n]
__device__ float    g_el[MAXH * N_NODES], g_er[MAXH * N_NODES];
__device__ unsigned g_Cbits[MAXH];                     // per-head max(er), order-preserving uint
__device__ __half   g_x16 [N_NODES * 128];             // layer-0 input, fp16
__device__ __half   g_bufA[N_NODES * 256];             // layer-0 output, fp16
__device__ __half   g_bufB[N_NODES * 256];             // layer-1 output, fp16
__device__ float    g_part[16 * N_NODES * 68];         // split-m partials (SPLIT*H <= 16 slabs)

// order-preserving float <-> uint mapping (exact max via atomicMax)
__device__ __forceinline__ unsigned fmap(float x) {
    unsigned b = __float_as_uint(x);
    return (b & 0x80000000u) ? ~b : (b | 0x80000000u);
}
__device__ __forceinline__ float funmap(unsigned m) {
    return __uint_as_float((m & 0x80000000u) ? (m & 0x7FFFFFFFu) : ~m);
}

// ---------------- adjacency -> bitmask ----------------
__global__ void k_mask(const int* __restrict__ adj, unsigned* __restrict__ maskw) {
    int n = blockIdx.x;
    int tid = threadIdx.x;
    const int* row = adj + (size_t)n * N_NODES;
#pragma unroll
    for (int it = 0; it < 4; it++) {
        int m = it * 1024 + tid;
        unsigned b = __ballot_sync(0xffffffffu, row[m] > 0);
        if ((tid & 31) == 0) maskw[n * 128 + (m >> 5)] = b;
    }
}

// ---------------- x fp32 -> fp16 (+ reset g_Cbits for layer 0) ----------------
__global__ void k_x2h(const float* __restrict__ in, __half* __restrict__ out, int n4) {
    if (blockIdx.x == 0 && threadIdx.x < MAXH) g_Cbits[threadIdx.x] = 0u;
    int i = blockIdx.x * 256 + threadIdx.x;
    if (i < n4) {
        float4 f = reinterpret_cast<const float4*>(in)[i];
        __half2 lo = __floats2half2_rn(f.x, f.y);
        __half2 hi = __floats2half2_rn(f.z, f.w);
        reinterpret_cast<uint2*>(out)[i] =
            make_uint2(*reinterpret_cast<unsigned*>(&lo), *reinterpret_cast<unsigned*>(&hi));
    }
}

__device__ __forceinline__ unsigned smem_u32(const void* p) {
    return (unsigned)__cvta_generic_to_shared(p);
}
__device__ __forceinline__ __half2 u2h(unsigned u) { return *reinterpret_cast<__half2*>(&u); }
__device__ __forceinline__ unsigned h2u(__half2 h) { return *reinterpret_cast<unsigned*>(&h); }

// ---------------- tensor-core feature GEMM + fused e_l/e_r + max(er) ----------------
template<int K>
__global__ void __launch_bounds__(256) k_feat_tc(
    const __half* __restrict__ in16, const float* __restrict__ W,
    const float* __restrict__ a,
    __half* __restrict__ h16T, float* __restrict__ el, float* __restrict__ er) {
    __shared__ __half As[128 * 72];    // [row][k] padded
    __shared__ __half WT[64 * 72];     // [o][k]  padded
    __shared__ float smax[8];
    const int h  = blockIdx.y;
    const int nb = blockIdx.x * 128;
    const int tid = threadIdx.x;
    const int lane = tid & 31, warp = tid >> 5;
    const int tig = lane & 3, gid = lane >> 2;
    const float* Wh = W + (size_t)h * K * 64;

    float acc[8][4];
#pragma unroll
    for (int i = 0; i < 8; i++)
#pragma unroll
        for (int j = 0; j < 4; j++) acc[i][j] = 0.f;

    const int arow = warp * 16 + (lane & 15);
    const unsigned aaddr = smem_u32(&As[arow * 72 + (lane >> 4) * 8]);

#pragma unroll 1
    for (int k0 = 0; k0 < K; k0 += 64) {
        __syncthreads();
#pragma unroll
        for (int i = 0; i < 4; i++) {
            int idx = tid + i * 256;       // 0..1023
            int r = idx >> 3, c = idx & 7;
            *reinterpret_cast<uint4*>(&As[r * 72 + c * 8]) =
                *reinterpret_cast<const uint4*>(in16 + (size_t)(nb + r) * K + k0 + c * 8);
        }
#pragma unroll
        for (int i = 0; i < 4; i++) {
            int idx = tid + i * 256;
            int kk = idx >> 4, og = (idx & 15) * 4;
            float4 w4 = *reinterpret_cast<const float4*>(&Wh[(size_t)(k0 + kk) * 64 + og]);
            WT[(og + 0) * 72 + kk] = __float2half_rn(w4.x);
            WT[(og + 1) * 72 + kk] = __float2half_rn(w4.y);
            WT[(og + 2) * 72 + kk] = __float2half_rn(w4.z);
            WT[(og + 3) * 72 + kk] = __float2half_rn(w4.w);
        }
        __syncthreads();
#pragma unroll
        for (int kc = 0; kc < 4; kc++) {
            unsigned a0, a1, a2, a3;
            asm volatile("ldmatrix.sync.aligned.m8n8.x4.shared.b16 {%0,%1,%2,%3}, [%4];\n"
                         : "=r"(a0), "=r"(a1), "=r"(a2), "=r"(a3)
                         : "r"(aaddr + kc * 32));
#pragma unroll
            for (int ncp = 0; ncp < 4; ncp++) {
                int g = lane >> 3, r = lane & 7;
                int brw  = ncp * 16 + (g >> 1) * 8 + r;
                int bcol = kc * 16 + (g & 1) * 8;
                unsigned baddr = smem_u32(&WT[brw * 72 + bcol]);
                unsigned b0, b1, b2, b3;
                asm volatile("ldmatrix.sync.aligned.m8n8.x4.shared.b16 {%0,%1,%2,%3}, [%4];\n"
                             : "=r"(b0), "=r"(b1), "=r"(b2), "=r"(b3) : "r"(baddr));
                asm volatile(
                    "mma.sync.aligned.m16n8k16.row.col.f32.f16.f16.f32 "
                    "{%0,%1,%2,%3}, {%4,%5,%6,%7}, {%8,%9}, {%0,%1,%2,%3};\n"
                    : "+f"(acc[2 * ncp][0]), "+f"(acc[2 * ncp][1]),
                      "+f"(acc[2 * ncp][2]), "+f"(acc[2 * ncp][3])
                    : "r"(a0), "r"(a1), "r"(a2), "r"(a3), "r"(b0), "r"(b1));
                asm volatile(
                    "mma.sync.aligned.m16n8k16.row.col.f32.f16.f16.f32 "
                    "{%0,%1,%2,%3}, {%4,%5,%6,%7}, {%8,%9}, {%0,%1,%2,%3};\n"
                    : "+f"(acc[2 * ncp + 1][0]), "+f"(acc[2 * ncp + 1][1]),
                      "+f"(acc[2 * ncp + 1][2]), "+f"(acc[2 * ncp + 1][3])
                    : "r"(a0), "r"(a1), "r"(a2), "r"(a3), "r"(b2), "r"(b3));
            }
        }
    }

    // ---- epilogue: h16T stores + el/er + CTA max(er) -> atomicMax ----
    const int n_lo = nb + warp * 16 + gid;
    const int n_hi = n_lo + 8;
    const int hb = h * N_NODES;
    __half* hTb = h16T + ((size_t)h * 64) * N_NODES;
    const float* ah = a + h * 128;

    float pl0 = 0.f, pl1 = 0.f, pr0 = 0.f, pr1 = 0.f;
#pragma unroll
    for (int nc = 0; nc < 8; nc++) {
        const int c0 = nc * 8 + 2 * tig;
        hTb[(size_t)c0 * N_NODES + n_lo]       = __float2half_rn(acc[nc][0]);
        hTb[(size_t)(c0 + 1) * N_NODES + n_lo] = __float2half_rn(acc[nc][1]);
        hTb[(size_t)c0 * N_NODES + n_hi]       = __float2half_rn(acc[nc][2]);
        hTb[(size_t)(c0 + 1) * N_NODES + n_hi] = __float2half_rn(acc[nc][3]);
        const float al0 = ah[c0], al1 = ah[c0 + 1];
        const float ar0 = ah[64 + c0], ar1 = ah[64 + c0 + 1];
        pl0 = fmaf(acc[nc][0], al0, fmaf(acc[nc][1], al1, pl0));
        pl1 = fmaf(acc[nc][2], al0, fmaf(acc[nc][3], al1, pl1));
        pr0 = fmaf(acc[nc][0], ar0, fmaf(acc[nc][1], ar1, pr0));
        pr1 = fmaf(acc[nc][2], ar0, fmaf(acc[nc][3], ar1, pr1));
    }
#pragma unroll
    for (int o = 1; o < 4; o <<= 1) {
        pl0 += __shfl_xor_sync(0xffffffffu, pl0, o);
        pl1 += __shfl_xor_sync(0xffffffffu, pl1, o);
        pr0 += __shfl_xor_sync(0xffffffffu, pr0, o);
        pr1 += __shfl_xor_sync(0xffffffffu, pr1, o);
    }
    if (tig == 0) {
        el[hb + n_lo] = pl0; el[hb + n_hi] = pl1;
        er[hb + n_lo] = pr0; er[hb + n_hi] = pr1;
    }
    // warp max of er (pr values valid in all lanes of each 4-lane group)
    float mx = fmaxf(pr0, pr1);
#pragma unroll
    for (int o = 4; o < 32; o <<= 1) mx = fmaxf(mx, __shfl_xor_sync(0xffffffffu, mx, o));
    if (lane == 0) smax[warp] = mx;
    __syncthreads();
    if (tid == 0) {
        float mm = smax[0];
#pragma unroll
        for (int i = 1; i < 8; i++) mm = fmaxf(mm, smax[i]);
        atomicMax(&g_Cbits[h], fmap(mm));
    }
}

// ---------------- fused flash-style attention (split-m): partials = W @ h, rowsum ----------------
// P/Q/G1/G2 computed in-prologue from el/er + g_Cbits (no separate kernel, no global round trip).
struct AttnSmem {
    __half hTs[2][64 * 136];    // double-buffered h tiles (cp.async), hT[o][m]  34816 B
    __half Ppk[2048], Qpk[2048];// CTA's own m-range of P/Q                       8192 B
};

#define CP_ASYNC16(dst_smem, src) \
    asm volatile("cp.async.cg.shared.global [%0], [%1], 16;" :: "r"(dst_smem), "l"(src))
#define CP_COMMIT() asm volatile("cp.async.commit_group;")
#define CP_WAIT0()  asm volatile("cp.async.wait_group 0;")

template<int SPLIT>
__global__ void __launch_bounds__(256, 3) k_attn(
    const __half* __restrict__ h16T,
    const float* __restrict__ elg, const float* __restrict__ erg,
    const unsigned* __restrict__ maskw,
    float* __restrict__ part, int H) {
    extern __shared__ char smem_raw[];
    AttnSmem& S = *reinterpret_cast<AttnSmem*>(smem_raw);

    constexpr int NTILES = (N_NODES / 128) / SPLIT;
    const int head = blockIdx.y;
    const int n0   = blockIdx.x * 128;
    const int tid  = threadIdx.x;
    const int lane = tid & 31, warp = tid >> 5;
    const int tig  = lane & 3, gid = lane >> 2;
    const int t2   = tig * 2;
    const int rA   = warp * 16 + gid;
    const int rB   = rA + 8;
    const int hb   = head * N_NODES;
    const int jbase = blockIdx.z * NTILES;
    const int mbase = jbase * 128;

    const float c = funmap(g_Cbits[head]);

    // stage this CTA's m-range of P/Q (computed from er; identical rounding to before)
    {
        constexpr int NM = NTILES * 128;
#pragma unroll
        for (int i = tid; i < NM; i += 256) {
            const float e_r = erg[hb + mbase + i];
            S.Ppk[i] = __float2half_rn(expf(e_r - c));
            S.Qpk[i] = __float2half_rn(expf(0.2f * (e_r - c)));
        }
    }
    // per-row gates
    const float zA = elg[hb + n0 + rA] + c;
    const float zB = elg[hb + n0 + rB] + c;
    const __half2 g1A = __float2half2_rn(zA > 0.f ? 1.f : expf(0.8f * zA));
    const __half2 g2A = __float2half2_rn(zA > 0.f ? expf(-0.8f * zA) : 1.f);
    const __half2 g1B = __float2half2_rn(zB > 0.f ? 1.f : expf(0.8f * zB));
    const __half2 g2B = __float2half2_rn(zB > 0.f ? expf(-0.8f * zB) : 1.f);

    float acc[8][4];
#pragma unroll
    for (int i = 0; i < 8; i++)
#pragma unroll
        for (int j = 0; j < 4; j++) acc[i][j] = 0.f;
    float acc_rs[4] = {0.f, 0.f, 0.f, 0.f};

    const __half* hT = h16T + (size_t)head * 64 * N_NODES;
    const unsigned* mrowA = maskw + (size_t)(n0 + rA) * 128;
    const unsigned* mrowB = maskw + (size_t)(n0 + rB) * 128;

    auto load_tile = [&](int j, int buf) {
        const int m0 = j * 128;
#pragma unroll
        for (int i = 0; i < 4; i++) {
            int idx = tid + i * 256;
            int r = idx >> 4, cc = idx & 15;
            unsigned dst = smem_u32(&S.hTs[buf][r * 136 + cc * 8]);
            CP_ASYNC16(dst, hT + (size_t)r * N_NODES + m0 + cc * 8);
        }
        CP_COMMIT();
    };

    load_tile(jbase, 0);
    uint4 pAq = *reinterpret_cast<const uint4*>(mrowA + ((jbase * 128) >> 5));
    uint4 pBq = *reinterpret_cast<const uint4*>(mrowB + ((jbase * 128) >> 5));

#pragma unroll 1
    for (int t = 0; t < NTILES; t++) {
        const int m0 = (jbase + t) * 128;
        const int ml = m0 - mbase;
        const int buf = t & 1;

        CP_WAIT0();
        __syncthreads();
        if (t + 1 < NTILES) load_tile(jbase + t + 1, buf ^ 1);

        const uint4 mAq = pAq, mBq = pBq;
        if (t + 1 < NTILES) {
            pAq = *reinterpret_cast<const uint4*>(mrowA + ((m0 + 128) >> 5));
            pBq = *reinterpret_cast<const uint4*>(mrowB + ((m0 + 128) >> 5));
        }
        const unsigned vA[4] = {mAq.x >> t2, mAq.y >> t2, mAq.z >> t2, mAq.w >> t2};
        const unsigned vB[4] = {mBq.x >> t2, mBq.y >> t2, mBq.z >> t2, mBq.w >> t2};

        const unsigned bone = 0x3C003C00u;
#pragma unroll
        for (int kc = 0; kc < 8; kc++) {
            const unsigned sh = (kc & 1) * 16;
            const unsigned wA = vA[kc >> 1] >> sh;
            const unsigned wB = vB[kc >> 1] >> sh;
            const unsigned b01A = wA & 3u,  b89A = (wA >> 8) & 3u;
            const unsigned b01B = wB & 3u,  b89B = (wB >> 8) & 3u;
            const unsigned m01A = ((b01A & 1u) ? 0x0000FFFFu : 0u) | ((b01A & 2u) ? 0xFFFF0000u : 0u);
            const unsigned m89A = ((b89A & 1u) ? 0x0000FFFFu : 0u) | ((b89A & 2u) ? 0xFFFF0000u : 0u);
            const unsigned m01B = ((b01B & 1u) ? 0x0000FFFFu : 0u) | ((b01B & 2u) ? 0xFFFF0000u : 0u);
            const unsigned m89B = ((b89B & 1u) ? 0x0000FFFFu : 0u) | ((b89B & 2u) ? 0xFFFF0000u : 0u);

            const int mloc = ml + kc * 16 + t2;
            const __half2 Pp  = *reinterpret_cast<const __half2*>(S.Ppk + mloc);
            const __half2 Pp8 = *reinterpret_cast<const __half2*>(S.Ppk + mloc + 8);
            const __half2 Qp  = *reinterpret_cast<const __half2*>(S.Qpk + mloc);
            const __half2 Qp8 = *reinterpret_cast<const __half2*>(S.Qpk + mloc + 8);

            const unsigned a0 = h2u(__hmax2(__hmul2(g1A, Pp ), __hmul2(g2A, Qp ))) & m01A;
            const unsigned a1 = h2u(__hmax2(__hmul2(g1B, Pp ), __hmul2(g2B, Qp ))) & m01B;
            const unsigned a2 = h2u(__hmax2(__hmul2(g1A, Pp8), __hmul2(g2A, Qp8))) & m89A;
            const unsigned a3 = h2u(__hmax2(__hmul2(g1B, Pp8), __hmul2(g2B, Qp8))) & m89B;

            asm volatile(
                "mma.sync.aligned.m16n8k16.row.col.f32.f16.f16.f32 "
                "{%0,%1,%2,%3}, {%4,%5,%6,%7}, {%8,%9}, {%0,%1,%2,%3};\n"
                : "+f"(acc_rs[0]), "+f"(acc_rs[1]), "+f"(acc_rs[2]), "+f"(acc_rs[3])
                : "r"(a0), "r"(a1), "r"(a2), "r"(a3), "r"(bone), "r"(bone));
#pragma unroll
            for (int ncp = 0; ncp < 4; ncp++) {
                int g = lane >> 3, r = lane & 7;
                int brw  = ncp * 16 + (g >> 1) * 8 + r;
                int bcol = kc * 16 + (g & 1) * 8;
                unsigned baddr = smem_u32(&S.hTs[buf][brw * 136 + bcol]);
                unsigned b0, b1, b2, b3;
                asm volatile("ldmatrix.sync.aligned.m8n8.x4.shared.b16 {%0,%1,%2,%3}, [%4];\n"
                             : "=r"(b0), "=r"(b1), "=r"(b2), "=r"(b3) : "r"(baddr));
                asm volatile(
                    "mma.sync.aligned.m16n8k16.row.col.f32.f16.f16.f32 "
                    "{%0,%1,%2,%3}, {%4,%5,%6,%7}, {%8,%9}, {%0,%1,%2,%3};\n"
                    : "+f"(acc[2 * ncp][0]), "+f"(acc[2 * ncp][1]),
                      "+f"(acc[2 * ncp][2]), "+f"(acc[2 * ncp][3])
                    : "r"(a0), "r"(a1), "r"(a2), "r"(a3), "r"(b0), "r"(b1));
                asm volatile(
                    "mma.sync.aligned.m16n8k16.row.col.f32.f16.f16.f32 "
                    "{%0,%1,%2,%3}, {%4,%5,%6,%7}, {%8,%9}, {%0,%1,%2,%3};\n"
                    : "+f"(acc[2 * ncp + 1][0]), "+f"(acc[2 * ncp + 1][1]),
                      "+f"(acc[2 * ncp + 1][2]), "+f"(acc[2 * ncp + 1][3])
                    : "r"(a0), "r"(a1), "r"(a2), "r"(a3), "r"(b2), "r"(b3));
            }
        }
    }

    float* pbase = part + (((size_t)blockIdx.z * H + head) * N_NODES + n0) * 68;
#pragma unroll
    for (int nc = 0; nc < 8; nc++) {
        int col = nc * 8 + t2;
        *reinterpret_cast<float2*>(pbase + (size_t)rA * 68 + col) = make_float2(acc[nc][0], acc[nc][1]);
        *reinterpret_cast<float2*>(pbase + (size_t)rB * 68 + col) = make_float2(acc[nc][2], acc[nc][3]);
    }
    if (tig == 0) {
        pbase[(size_t)rA * 68 + 64] = acc_rs[0];
        pbase[(size_t)rB * 68 + 64] = acc_rs[2];
    }
}

// ---------------- combine split-m partials: divide + optional ELU; fp16 or fp32 out ----------------
// Also resets g_Cbits for the NEXT layer's feature kernel.
template<bool HALF_OUT>
__global__ void k_combine(const float* __restrict__ part, float* __restrict__ fout,
                          __half* __restrict__ hout,
                          int H, int SPLIT, int outStride, int applyElu) {
    if (blockIdx.x == 0 && threadIdx.x < MAXH) g_Cbits[threadIdx.x] = 0u;
    const int idx = blockIdx.x * 256 + threadIdx.x;    // over H*N*64
    const int o = idx & 63, n = (idx >> 6) & (N_NODES - 1), head = idx >> 18;
    float s = 0.f, r = 0.f;
    for (int z = 0; z < SPLIT; z++) {
        const float* pb = part + (((size_t)z * H + head) * N_NODES + n) * 68;
        s += pb[o];
        r += pb[64];
    }
    float v = s / r;
    if (applyElu) v = v > 0.f ? v : expm1f(v);
    if (HALF_OUT) hout[(size_t)n * outStride + head * 64 + o] = __float2half_rn(v);
    else          fout[(size_t)n * outStride + head * 64 + o] = v;
}

// ---------------- host orchestration ----------------
struct Scratch {
    unsigned* maskw; __half* h16T;
    float *el, *er, *part;
    __half *x16, *bufA, *bufB;
};

static void run_layer(const __half* in16, int K, const float* W, const float* a, int H,
                      float* foutp, __half* houtp, int outStride, int applyElu,
                      const Scratch& s) {
    if (K == 128) k_feat_tc<128><<<dim3(N_NODES / 128, H), 256>>>(in16, W, a, s.h16T, s.el, s.er);
    else          k_feat_tc<256><<<dim3(N_NODES / 128, H), 256>>>(in16, W, a, s.h16T, s.el, s.er);
    if (H == 4) {
        k_attn<4><<<dim3(N_NODES / 128, H, 4), 256, sizeof(AttnSmem)>>>(
            s.h16T, s.el, s.er, s.maskw, s.part, H);
        if (houtp) k_combine<true ><<<H * N_NODES * 64 / 256, 256>>>(s.part, foutp, houtp, H, 4, outStride, applyElu);
        else       k_combine<false><<<H * N_NODES * 64 / 256, 256>>>(s.part, foutp, houtp, H, 4, outStride, applyElu);
    } else {
        k_attn<8><<<dim3(N_NODES / 128, H, 8), 256, sizeof(AttnSmem)>>>(
            s.h16T, s.el, s.er, s.maskw, s.part, H);
        if (houtp) k_combine<true ><<<H * N_NODES * 64 / 256, 256>>>(s.part, foutp, houtp, H, 8, outStride, applyElu);
        else       k_combine<false><<<H * N_NODES * 64 / 256, 256>>>(s.part, foutp, houtp, H, 8, outStride, applyElu);
    }
}

extern "C" void kernel_launch(void* const* d_in, const int* in_sizes, int n_in,
                              void* d_out, int out_size) {
    (void)in_sizes; (void)n_in; (void)out_size;
    const float* x  = (const float*)d_in[0];
    const int*   adj = (const int*)d_in[1];
    const float* W0 = (const float*)d_in[2];
    const float* a0 = (const float*)d_in[3];
    const float* W1 = (const float*)d_in[4];
    const float* a1 = (const float*)d_in[5];
    const float* W2 = (const float*)d_in[6];
    const float* a2 = (const float*)d_in[7];

    cudaFuncSetAttribute(k_attn<4>, cudaFuncAttributeMaxDynamicSharedMemorySize,
                         (int)sizeof(AttnSmem));
    cudaFuncSetAttribute(k_attn<8>, cudaFuncAttributeMaxDynamicSharedMemorySize,
                         (int)sizeof(AttnSmem));

    Scratch s;
    void* p;
    cudaGetSymbolAddress(&p, g_maskw); s.maskw = (unsigned*)p;
    cudaGetSymbolAddress(&p, g_h16T);  s.h16T  = (__half*)p;
    cudaGetSymbolAddress(&p, g_el);    s.el    = (float*)p;
    cudaGetSymbolAddress(&p, g_er);    s.er    = (float*)p;
    cudaGetSymbolAddress(&p, g_part);  s.part  = (float*)p;
    cudaGetSymbolAddress(&p, g_x16);   s.x16   = (__half*)p;
    cudaGetSymbolAddress(&p, g_bufA);  s.bufA  = (__half*)p;
    cudaGetSymbolAddress(&p, g_bufB);  s.bufB  = (__half*)p;

    k_mask<<<N_NODES, 1024>>>(adj, s.maskw);
    k_x2h<<<(N_NODES * 128 / 4 + 255) / 256, 256>>>(x, s.x16, N_NODES * 128 / 4);

    run_layer(s.x16,  128, W0, a0, 4, nullptr,        s.bufA, 256, 1, s);
    run_layer(s.bufA, 256, W1, a1, 4, nullptr,        s.bufB, 256, 1, s);
    run_layer(s.bufB, 256, W2, a2, 1, (float*)d_out,  nullptr, 64, 0, s);
}

// round 13
// speedup vs baseline: 1.2719x; 1.0467x over previous
#include <cuda_runtime.h>
#include <cuda_fp16.h>
#include <cstdint>

#define N_NODES 4096
#define MAXH 4

// ---------------- scratch (static device globals; no allocation) ----------------
__device__ unsigned g_maskw[N_NODES * 128];            // 2 MB adjacency bitmask
__device__ __half   g_h16T [MAXH * 64 * N_NODES];      // per-head features fp16, transposed [h][o][n]
__device__ float    g_el[MAXH * N_NODES], g_er[MAXH * N_NODES];
__device__ unsigned g_Cbits[MAXH];                     // per-head max(er), order-preserving uint
__device__ __half   g_x16 [N_NODES * 128];             // layer-0 input, fp16
__device__ __half   g_bufA[N_NODES * 256];             // layer-0 output, fp16
__device__ __half   g_bufB[N_NODES * 256];             // layer-1 output, fp16
__device__ float    g_part[16 * N_NODES * 68];         // split-m partials (SPLIT*H <= 16 slabs)

// order-preserving float <-> uint mapping (exact max via atomicMax)
__device__ __forceinline__ unsigned fmap(float x) {
    unsigned b = __float_as_uint(x);
    return (b & 0x80000000u) ? ~b : (b | 0x80000000u);
}
__device__ __forceinline__ float funmap(unsigned m) {
    return __uint_as_float((m & 0x80000000u) ? (m & 0x7FFFFFFFu) : ~m);
}

// ---------------- adjacency -> bitmask ----------------
__global__ void k_mask(const int* __restrict__ adj, unsigned* __restrict__ maskw) {
    int n = blockIdx.x;
    int tid = threadIdx.x;
    const int* row = adj + (size_t)n * N_NODES;
#pragma unroll
    for (int it = 0; it < 4; it++) {
        int m = it * 1024 + tid;
        unsigned b = __ballot_sync(0xffffffffu, row[m] > 0);
        if ((tid & 31) == 0) maskw[n * 128 + (m >> 5)] = b;
    }
}

// ---------------- x fp32 -> fp16 (+ reset g_Cbits for layer 0) ----------------
__global__ void k_x2h(const float* __restrict__ in, __half* __restrict__ out, int n4) {
    if (blockIdx.x == 0 && threadIdx.x < MAXH) g_Cbits[threadIdx.x] = 0u;
    int i = blockIdx.x * 256 + threadIdx.x;
    if (i < n4) {
        float4 f = reinterpret_cast<const float4*>(in)[i];
        __half2 lo = __floats2half2_rn(f.x, f.y);
        __half2 hi = __floats2half2_rn(f.z, f.w);
        reinterpret_cast<uint2*>(out)[i] =
            make_uint2(*reinterpret_cast<unsigned*>(&lo), *reinterpret_cast<unsigned*>(&hi));
    }
}

__device__ __forceinline__ unsigned smem_u32(const void* p) {
    return (unsigned)__cvta_generic_to_shared(p);
}
__device__ __forceinline__ __half2 u2h(unsigned u) { return *reinterpret_cast<__half2*>(&u); }
__device__ __forceinline__ unsigned h2u(__half2 h) { return *reinterpret_cast<unsigned*>(&h); }

// ---------------- tensor-core feature GEMM + fused e_l/e_r + max(er) ----------------
template<int K>
__global__ void __launch_bounds__(256) k_feat_tc(
    const __half* __restrict__ in16, const float* __restrict__ W,
    const float* __restrict__ a,
    __half* __restrict__ h16T, float* __restrict__ el, float* __restrict__ er) {
    __shared__ __half As[128 * 72];    // [row][k] padded
    __shared__ __half WT[64 * 72];     // [o][k]  padded
    __shared__ float smax[8];
    const int h  = blockIdx.y;
    const int nb = blockIdx.x * 128;
    const int tid = threadIdx.x;
    const int lane = tid & 31, warp = tid >> 5;
    const int tig = lane & 3, gid = lane >> 2;
    const float* Wh = W + (size_t)h * K * 64;

    float acc[8][4];
#pragma unroll
    for (int i = 0; i < 8; i++)
#pragma unroll
        for (int j = 0; j < 4; j++) acc[i][j] = 0.f;

    const int arow = warp * 16 + (lane & 15);
    const unsigned aaddr = smem_u32(&As[arow * 72 + (lane >> 4) * 8]);

#pragma unroll 1
    for (int k0 = 0; k0 < K; k0 += 64) {
        __syncthreads();
#pragma unroll
        for (int i = 0; i < 4; i++) {
            int idx = tid + i * 256;       // 0..1023
            int r = idx >> 3, c = idx & 7;
            *reinterpret_cast<uint4*>(&As[r * 72 + c * 8]) =
                *reinterpret_cast<const uint4*>(in16 + (size_t)(nb + r) * K + k0 + c * 8);
        }
#pragma unroll
        for (int i = 0; i < 4; i++) {
            int idx = tid + i * 256;
            int kk = idx >> 4, og = (idx & 15) * 4;
            float4 w4 = *reinterpret_cast<const float4*>(&Wh[(size_t)(k0 + kk) * 64 + og]);
            WT[(og + 0) * 72 + kk] = __float2half_rn(w4.x);
            WT[(og + 1) * 72 + kk] = __float2half_rn(w4.y);
            WT[(og + 2) * 72 + kk] = __float2half_rn(w4.z);
            WT[(og + 3) * 72 + kk] = __float2half_rn(w4.w);
        }
        __syncthreads();
#pragma unroll
        for (int kc = 0; kc < 4; kc++) {
            unsigned a0, a1, a2, a3;
            asm volatile("ldmatrix.sync.aligned.m8n8.x4.shared.b16 {%0,%1,%2,%3}, [%4];\n"
                         : "=r"(a0), "=r"(a1), "=r"(a2), "=r"(a3)
                         : "r"(aaddr + kc * 32));
#pragma unroll
            for (int ncp = 0; ncp < 4; ncp++) {
                int g = lane >> 3, r = lane & 7;
                int brw  = ncp * 16 + (g >> 1) * 8 + r;
                int bcol = kc * 16 + (g & 1) * 8;
                unsigned baddr = smem_u32(&WT[brw * 72 + bcol]);
                unsigned b0, b1, b2, b3;
                asm volatile("ldmatrix.sync.aligned.m8n8.x4.shared.b16 {%0,%1,%2,%3}, [%4];\n"
                             : "=r"(b0), "=r"(b1), "=r"(b2), "=r"(b3) : "r"(baddr));
                asm volatile(
                    "mma.sync.aligned.m16n8k16.row.col.f32.f16.f16.f32 "
                    "{%0,%1,%2,%3}, {%4,%5,%6,%7}, {%8,%9}, {%0,%1,%2,%3};\n"
                    : "+f"(acc[2 * ncp][0]), "+f"(acc[2 * ncp][1]),
                      "+f"(acc[2 * ncp][2]), "+f"(acc[2 * ncp][3])
                    : "r"(a0), "r"(a1), "r"(a2), "r"(a3), "r"(b0), "r"(b1));
                asm volatile(
                    "mma.sync.aligned.m16n8k16.row.col.f32.f16.f16.f32 "
                    "{%0,%1,%2,%3}, {%4,%5,%6,%7}, {%8,%9}, {%0,%1,%2,%3};\n"
                    : "+f"(acc[2 * ncp + 1][0]), "+f"(acc[2 * ncp + 1][1]),
                      "+f"(acc[2 * ncp + 1][2]), "+f"(acc[2 * ncp + 1][3])
                    : "r"(a0), "r"(a1), "r"(a2), "r"(a3), "r"(b2), "r"(b3));
            }
        }
    }

    // ---- epilogue: h16T stores + el/er + CTA max(er) -> atomicMax ----
    const int n_lo = nb + warp * 16 + gid;
    const int n_hi = n_lo + 8;
    const int hb = h * N_NODES;
    __half* hTb = h16T + ((size_t)h * 64) * N_NODES;
    const float* ah = a + h * 128;

    float pl0 = 0.f, pl1 = 0.f, pr0 = 0.f, pr1 = 0.f;
#pragma unroll
    for (int nc = 0; nc < 8; nc++) {
        const int c0 = nc * 8 + 2 * tig;
        hTb[(size_t)c0 * N_NODES + n_lo]       = __float2half_rn(acc[nc][0]);
        hTb[(size_t)(c0 + 1) * N_NODES + n_lo] = __float2half_rn(acc[nc][1]);
        hTb[(size_t)c0 * N_NODES + n_hi]       = __float2half_rn(acc[nc][2]);
        hTb[(size_t)(c0 + 1) * N_NODES + n_hi] = __float2half_rn(acc[nc][3]);
        const float al0 = ah[c0], al1 = ah[c0 + 1];
        const float ar0 = ah[64 + c0], ar1 = ah[64 + c0 + 1];
        pl0 = fmaf(acc[nc][0], al0, fmaf(acc[nc][1], al1, pl0));
        pl1 = fmaf(acc[nc][2], al0, fmaf(acc[nc][3], al1, pl1));
        pr0 = fmaf(acc[nc][0], ar0, fmaf(acc[nc][1], ar1, pr0));
        pr1 = fmaf(acc[nc][2], ar0, fmaf(acc[nc][3], ar1, pr1));
    }
#pragma unroll
    for (int o = 1; o < 4; o <<= 1) {
        pl0 += __shfl_xor_sync(0xffffffffu, pl0, o);
        pl1 += __shfl_xor_sync(0xffffffffu, pl1, o);
        pr0 += __shfl_xor_sync(0xffffffffu, pr0, o);
        pr1 += __shfl_xor_sync(0xffffffffu, pr1, o);
    }
    if (tig == 0) {
        el[hb + n_lo] = pl0; el[hb + n_hi] = pl1;
        er[hb + n_lo] = pr0; er[hb + n_hi] = pr1;
    }
    // warp max of er (pr values valid in all lanes of each 4-lane group)
    float mx = fmaxf(pr0, pr1);
#pragma unroll
    for (int o = 4; o < 32; o <<= 1) mx = fmaxf(mx, __shfl_xor_sync(0xffffffffu, mx, o));
    if (lane == 0) smax[warp] = mx;
    __syncthreads();
    if (tid == 0) {
        float mm = smax[0];
#pragma unroll
        for (int i = 1; i < 8; i++) mm = fmaxf(mm, smax[i]);
        atomicMax(&g_Cbits[h], fmap(mm));
    }
}

// ---------------- fused flash-style attention (split-m): partials = W @ h, rowsum ----------------
// P/Q staged in fragment-pair-permuted order (one LDS.64 = both half2 fragments);
// adjacency masks via 4-bit-index smem LUT (conflict-free, full-warp replicated).
struct AttnSmem {
    __half hTs[2][64 * 136];    // double-buffered h tiles (cp.async), hT[o][m]  34816 B
    __half Ppk[2048], Qpk[2048];// CTA's m-range of P/Q, permuted                 8192 B
    uint2  lut[16 * 32];        // 4-bit mask index -> (m01, m89)                 4096 B
};

#define CP_ASYNC16(dst_smem, src) \
    asm volatile("cp.async.cg.shared.global [%0], [%1], 16;" :: "r"(dst_smem), "l"(src))
#define CP_COMMIT() asm volatile("cp.async.commit_group;")
#define CP_WAIT0()  asm volatile("cp.async.wait_group 0;")

template<int SPLIT>
__global__ void __launch_bounds__(256, 3) k_attn(
    const __half* __restrict__ h16T,
    const float* __restrict__ elg, const float* __restrict__ erg,
    const unsigned* __restrict__ maskw,
    float* __restrict__ part, int H) {
    extern __shared__ char smem_raw[];
    AttnSmem& S = *reinterpret_cast<AttnSmem*>(smem_raw);

    constexpr int NTILES = (N_NODES / 128) / SPLIT;
    const int head = blockIdx.y;
    const int n0   = blockIdx.x * 128;
    const int tid  = threadIdx.x;
    const int lane = tid & 31, warp = tid >> 5;
    const int tig  = lane & 3, gid = lane >> 2;
    const int t2   = tig * 2;
    const int rA   = warp * 16 + gid;
    const int rB   = rA + 8;
    const int hb   = head * N_NODES;
    const int jbase = blockIdx.z * NTILES;
    const int mbase = jbase * 128;

    const float c = funmap(g_Cbits[head]);

    // stage P/Q (permuted within 16-groups: [0,1,8,9, 2,3,10,11, 4,5,12,13, 6,7,14,15])
    {
        constexpr int NM = NTILES * 128;
#pragma unroll
        for (int i = tid; i < NM; i += 256) {
            const float e_r = erg[hb + mbase + i];
            const int grp = i >> 4, ii = i & 15;
            const int pos = (ii < 8) ? ((ii >> 1) * 4 + (ii & 1))
                                     : (((ii - 8) >> 1) * 4 + 2 + (ii & 1));
            const int d = (grp << 4) + pos;
            S.Ppk[d] = __float2half_rn(expf(e_r - c));
            S.Qpk[d] = __float2half_rn(expf(0.2f * (e_r - c)));
        }
        // mask LUT: idx bits {0,1} -> m01 halves, bits {2,3} -> m89 halves
#pragma unroll
        for (int i = tid; i < 512; i += 256) {
            const int idx = i >> 5;
            unsigned m01 = ((idx & 1) ? 0x0000FFFFu : 0u) | ((idx & 2) ? 0xFFFF0000u : 0u);
            unsigned m89 = ((idx & 4) ? 0x0000FFFFu : 0u) | ((idx & 8) ? 0xFFFF0000u : 0u);
            S.lut[i] = make_uint2(m01, m89);
        }
    }
    // per-row gates
    const float zA = elg[hb + n0 + rA] + c;
    const float zB = elg[hb + n0 + rB] + c;
    const __half2 g1A = __float2half2_rn(zA > 0.f ? 1.f : expf(0.8f * zA));
    const __half2 g2A = __float2half2_rn(zA > 0.f ? expf(-0.8f * zA) : 1.f);
    const __half2 g1B = __float2half2_rn(zB > 0.f ? 1.f : expf(0.8f * zB));
    const __half2 g2B = __float2half2_rn(zB > 0.f ? expf(-0.8f * zB) : 1.f);

    float acc[8][4];
#pragma unroll
    for (int i = 0; i < 8; i++)
#pragma unroll
        for (int j = 0; j < 4; j++) acc[i][j] = 0.f;
    float acc_rs[4] = {0.f, 0.f, 0.f, 0.f};

    const __half* hT = h16T + (size_t)head * 64 * N_NODES;
    const unsigned* mrowA = maskw + (size_t)(n0 + rA) * 128;
    const unsigned* mrowB = maskw + (size_t)(n0 + rB) * 128;

    auto load_tile = [&](int j, int buf) {
        const int m0 = j * 128;
#pragma unroll
        for (int i = 0; i < 4; i++) {
            int idx = tid + i * 256;
            int r = idx >> 4, cc = idx & 15;
            unsigned dst = smem_u32(&S.hTs[buf][r * 136 + cc * 8]);
            CP_ASYNC16(dst, hT + (size_t)r * N_NODES + m0 + cc * 8);
        }
        CP_COMMIT();
    };

    load_tile(jbase, 0);
    uint4 pAq = *reinterpret_cast<const uint4*>(mrowA + ((jbase * 128) >> 5));
    uint4 pBq = *reinterpret_cast<const uint4*>(mrowB + ((jbase * 128) >> 5));

#pragma unroll 1
    for (int t = 0; t < NTILES; t++) {
        const int m0 = (jbase + t) * 128;
        const int ml = m0 - mbase;
        const int buf = t & 1;

        CP_WAIT0();
        __syncthreads();
        if (t + 1 < NTILES) load_tile(jbase + t + 1, buf ^ 1);

        const uint4 mAq = pAq, mBq = pBq;
        if (t + 1 < NTILES) {
            pAq = *reinterpret_cast<const uint4*>(mrowA + ((m0 + 128) >> 5));
            pBq = *reinterpret_cast<const uint4*>(mrowB + ((m0 + 128) >> 5));
        }
        const unsigned vA[4] = {mAq.x >> t2, mAq.y >> t2, mAq.z >> t2, mAq.w >> t2};
        const unsigned vB[4] = {mBq.x >> t2, mBq.y >> t2, mBq.z >> t2, mBq.w >> t2};

        const unsigned bone = 0x3C003C00u;
#pragma unroll
        for (int kc = 0; kc < 8; kc++) {
            const unsigned sh = (kc & 1) * 16;
            const unsigned wA = vA[kc >> 1] >> sh;
            const unsigned wB = vB[kc >> 1] >> sh;
            // 4-bit index over bits {0,1,8,9} -> LUT gives both masks
            const unsigned iA = (wA & 3u) | ((wA >> 6) & 12u);
            const unsigned iB = (wB & 3u) | ((wB >> 6) & 12u);
            const uint2 mA = S.lut[(iA << 5) | lane];
            const uint2 mB = S.lut[(iB << 5) | lane];

            // one LDS.64 each: (P_t2,P_t2+1 | P_t2+8,P_t2+9) via permuted layout
            const int eoff = ml + kc * 16 + 4 * tig;
            const uint2 pv = *reinterpret_cast<const uint2*>(S.Ppk + eoff);
            const uint2 qv = *reinterpret_cast<const uint2*>(S.Qpk + eoff);

            const unsigned a0 = h2u(__hmax2(__hmul2(g1A, u2h(pv.x)), __hmul2(g2A, u2h(qv.x)))) & mA.x;
            const unsigned a1 = h2u(__hmax2(__hmul2(g1B, u2h(pv.x)), __hmul2(g2B, u2h(qv.x)))) & mB.x;
            const unsigned a2 = h2u(__hmax2(__hmul2(g1A, u2h(pv.y)), __hmul2(g2A, u2h(qv.y)))) & mA.y;
            const unsigned a3 = h2u(__hmax2(__hmul2(g1B, u2h(pv.y)), __hmul2(g2B, u2h(qv.y)))) & mB.y;

            asm volatile(
                "mma.sync.aligned.m16n8k16.row.col.f32.f16.f16.f32 "
                "{%0,%1,%2,%3}, {%4,%5,%6,%7}, {%8,%9}, {%0,%1,%2,%3};\n"
                : "+f"(acc_rs[0]), "+f"(acc_rs[1]), "+f"(acc_rs[2]), "+f"(acc_rs[3])
                : "r"(a0), "r"(a1), "r"(a2), "r"(a3), "r"(bone), "r"(bone));
#pragma unroll
            for (int ncp = 0; ncp < 4; ncp++) {
                int g = lane >> 3, r = lane & 7;
                int brw  = ncp * 16 + (g >> 1) * 8 + r;
                int bcol = kc * 16 + (g & 1) * 8;
                unsigned baddr = smem_u32(&S.hTs[buf][brw * 136 + bcol]);
                unsigned b0, b1, b2, b3;
                asm volatile("ldmatrix.sync.aligned.m8n8.x4.shared.b16 {%0,%1,%2,%3}, [%4];\n"
                             : "=r"(b0), "=r"(b1), "=r"(b2), "=r"(b3) : "r"(baddr));
                asm volatile(
                    "mma.sync.aligned.m16n8k16.row.col.f32.f16.f16.f32 "
                    "{%0,%1,%2,%3}, {%4,%5,%6,%7}, {%8,%9}, {%0,%1,%2,%3};\n"
                    : "+f"(acc[2 * ncp][0]), "+f"(acc[2 * ncp][1]),
                      "+f"(acc[2 * ncp][2]), "+f"(acc[2 * ncp][3])
                    : "r"(a0), "r"(a1), "r"(a2), "r"(a3), "r"(b0), "r"(b1));
                asm volatile(
                    "mma.sync.aligned.m16n8k16.row.col.f32.f16.f16.f32 "
                    "{%0,%1,%2,%3}, {%4,%5,%6,%7}, {%8,%9}, {%0,%1,%2,%3};\n"
                    : "+f"(acc[2 * ncp + 1][0]), "+f"(acc[2 * ncp + 1][1]),
                      "+f"(acc[2 * ncp + 1][2]), "+f"(acc[2 * ncp + 1][3])
                    : "r"(a0), "r"(a1), "r"(a2), "r"(a3), "r"(b2), "r"(b3));
            }
        }
    }

    float* pbase = part + (((size_t)blockIdx.z * H + head) * N_NODES + n0) * 68;
#pragma unroll
    for (int nc = 0; nc < 8; nc++) {
        int col = nc * 8 + t2;
        *reinterpret_cast<float2*>(pbase + (size_t)rA * 68 + col) = make_float2(acc[nc][0], acc[nc][1]);
        *reinterpret_cast<float2*>(pbase + (size_t)rB * 68 + col) = make_float2(acc[nc][2], acc[nc][3]);
    }
    if (tig == 0) {
        pbase[(size_t)rA * 68 + 64] = acc_rs[0];
        pbase[(size_t)rB * 68 + 64] = acc_rs[2];
    }
}

// ---------------- combine split-m partials: divide + optional ELU; fp16 or fp32 out ----------------
// Also resets g_Cbits for the NEXT layer's feature kernel.
template<bool HALF_OUT>
__global__ void k_combine(const float* __restrict__ part, float* __restrict__ fout,
                          __half* __restrict__ hout,
                          int H, int SPLIT, int outStride, int applyElu) {
    if (blockIdx.x == 0 && threadIdx.x < MAXH) g_Cbits[threadIdx.x] = 0u;
    const int idx = blockIdx.x * 256 + threadIdx.x;    // over H*N*64
    const int o = idx & 63, n = (idx >> 6) & (N_NODES - 1), head = idx >> 18;
    float s = 0.f, r = 0.f;
    for (int z = 0; z < SPLIT; z++) {
        const float* pb = part + (((size_t)z * H + head) * N_NODES + n) * 68;
        s += pb[o];
        r += pb[64];
    }
    float v = s / r;
    if (applyElu) v = v > 0.f ? v : expm1f(v);
    if (HALF_OUT) hout[(size_t)n * outStride + head * 64 + o] = __float2half_rn(v);
    else          fout[(size_t)n * outStride + head * 64 + o] = v;
}

// ---------------- host orchestration ----------------
struct Scratch {
    unsigned* maskw; __half* h16T;
    float *el, *er, *part;
    __half *x16, *bufA, *bufB;
};

static void run_layer(const __half* in16, int K, const float* W, const float* a, int H,
                      float* foutp, __half* houtp, int outStride, int applyElu,
                      const Scratch& s) {
    if (K == 128) k_feat_tc<128><<<dim3(N_NODES / 128, H), 256>>>(in16, W, a, s.h16T, s.el, s.er);
    else          k_feat_tc<256><<<dim3(N_NODES / 128, H), 256>>>(in16, W, a, s.h16T, s.el, s.er);
    if (H == 4) {
        k_attn<4><<<dim3(N_NODES / 128, H, 4), 256, sizeof(AttnSmem)>>>(
            s.h16T, s.el, s.er, s.maskw, s.part, H);
        if (houtp) k_combine<true ><<<H * N_NODES * 64 / 256, 256>>>(s.part, foutp, houtp, H, 4, outStride, applyElu);
        else       k_combine<false><<<H * N_NODES * 64 / 256, 256>>>(s.part, foutp, houtp, H, 4, outStride, applyElu);
    } else {
        k_attn<8><<<dim3(N_NODES / 128, H, 8), 256, sizeof(AttnSmem)>>>(
            s.h16T, s.el, s.er, s.maskw, s.part, H);
        if (houtp) k_combine<true ><<<H * N_NODES * 64 / 256, 256>>>(s.part, foutp, houtp, H, 8, outStride, applyElu);
        else       k_combine<false><<<H * N_NODES * 64 / 256, 256>>>(s.part, foutp, houtp, H, 8, outStride, applyElu);
    }
}

extern "C" void kernel_launch(void* const* d_in, const int* in_sizes, int n_in,
                              void* d_out, int out_size) {
    (void)in_sizes; (void)n_in; (void)out_size;
    const float* x  = (const float*)d_in[0];
    const int*   adj = (const int*)d_in[1];
    const float* W0 = (const float*)d_in[2];
    const float* a0 = (const float*)d_in[3];
    const float* W1 = (const float*)d_in[4];
    const float* a1 = (const float*)d_in[5];
    const float* W2 = (const float*)d_in[6];
    const float* a2 = (const float*)d_in[7];

    cudaFuncSetAttribute(k_attn<4>, cudaFuncAttributeMaxDynamicSharedMemorySize,
                         (int)sizeof(AttnSmem));
    cudaFuncSetAttribute(k_attn<8>, cudaFuncAttributeMaxDynamicSharedMemorySize,
                         (int)sizeof(AttnSmem));

    Scratch s;
    void* p;
    cudaGetSymbolAddress(&p, g_maskw); s.maskw = (unsigned*)p;
    cudaGetSymbolAddress(&p, g_h16T);  s.h16T  = (__half*)p;
    cudaGetSymbolAddress(&p, g_el);    s.el    = (float*)p;
    cudaGetSymbolAddress(&p, g_er);    s.er    = (float*)p;
    cudaGetSymbolAddress(&p, g_part);  s.part  = (float*)p;
    cudaGetSymbolAddress(&p, g_x16);   s.x16   = (__half*)p;
    cudaGetSymbolAddress(&p, g_bufA);  s.bufA  = (__half*)p;
    cudaGetSymbolAddress(&p, g_bufB);  s.bufB  = (__half*)p;

    k_mask<<<N_NODES, 1024>>>(adj, s.maskw);
    k_x2h<<<(N_NODES * 128 / 4 + 255) / 256, 256>>>(x, s.x16, N_NODES * 128 / 4);

    run_layer(s.x16,  128, W0, a0, 4, nullptr,        s.bufA, 256, 1, s);
    run_layer(s.bufA, 256, W1, a1, 4, nullptr,        s.bufB, 256, 1, s);
    run_layer(s.bufB, 256, W2, a2, 1, (float*)d_out,  nullptr, 64, 0, s);
}

// round 14
// speedup vs baseline: 1.2910x; 1.0150x over previous
#include <cuda_runtime.h>
#include <cuda_fp16.h>
#include <cstdint>

#define N_NODES 4096
#define MAXH 4

// ---------------- scratch (static device globals; no allocation) ----------------
__device__ unsigned g_maskw[N_NODES * 128];            // 2 MB adjacency bitmask
__device__ __half   g_h16T [MAXH * 64 * N_NODES];      // per-head features fp16, transposed [h][o][n]
__device__ float    g_el[MAXH * N_NODES], g_er[MAXH * N_NODES];
__device__ unsigned g_Cbits[MAXH];                     // per-head max(er), order-preserving uint
__device__ __half   g_x16 [N_NODES * 128];             // layer-0 input, fp16
__device__ __half   g_bufA[N_NODES * 256];             // layer-0 output, fp16
__device__ __half   g_bufB[N_NODES * 256];             // layer-1 output, fp16
__device__ float    g_part[16 * N_NODES * 68];         // split-m partials (SPLIT*H <= 16 slabs)

// order-preserving float <-> uint mapping (exact max via atomicMax)
__device__ __forceinline__ unsigned fmap(float x) {
    unsigned b = __float_as_uint(x);
    return (b & 0x80000000u) ? ~b : (b | 0x80000000u);
}
__device__ __forceinline__ float funmap(unsigned m) {
    return __uint_as_float((m & 0x80000000u) ? (m & 0x7FFFFFFFu) : ~m);
}

// ---------------- adjacency -> bitmask ----------------
__global__ void k_mask(const int* __restrict__ adj, unsigned* __restrict__ maskw) {
    int n = blockIdx.x;
    int tid = threadIdx.x;
    const int* row = adj + (size_t)n * N_NODES;
#pragma unroll
    for (int it = 0; it < 4; it++) {
        int m = it * 1024 + tid;
        unsigned b = __ballot_sync(0xffffffffu, row[m] > 0);
        if ((tid & 31) == 0) maskw[n * 128 + (m >> 5)] = b;
    }
}

// ---------------- x fp32 -> fp16 (+ reset g_Cbits for layer 0) ----------------
__global__ void k_x2h(const float* __restrict__ in, __half* __restrict__ out, int n4) {
    if (blockIdx.x == 0 && threadIdx.x < MAXH) g_Cbits[threadIdx.x] = 0u;
    int i = blockIdx.x * 256 + threadIdx.x;
    if (i < n4) {
        float4 f = reinterpret_cast<const float4*>(in)[i];
        __half2 lo = __floats2half2_rn(f.x, f.y);
        __half2 hi = __floats2half2_rn(f.z, f.w);
        reinterpret_cast<uint2*>(out)[i] =
            make_uint2(*reinterpret_cast<unsigned*>(&lo), *reinterpret_cast<unsigned*>(&hi));
    }
}

__device__ __forceinline__ unsigned smem_u32(const void* p) {
    return (unsigned)__cvta_generic_to_shared(p);
}
__device__ __forceinline__ __half2 u2h(unsigned u) { return *reinterpret_cast<__half2*>(&u); }
__device__ __forceinline__ unsigned h2u(__half2 h) { return *reinterpret_cast<unsigned*>(&h); }

// ---------------- tensor-core feature GEMM + fused e_l/e_r + max(er) ----------------
template<int K>
__global__ void __launch_bounds__(256) k_feat_tc(
    const __half* __restrict__ in16, const float* __restrict__ W,
    const float* __restrict__ a,
    __half* __restrict__ h16T, float* __restrict__ el, float* __restrict__ er) {
    __shared__ __half As[128 * 72];    // [row][k] padded
    __shared__ __half WT[64 * 72];     // [o][k]  padded
    __shared__ float smax[8];
    const int h  = blockIdx.y;
    const int nb = blockIdx.x * 128;
    const int tid = threadIdx.x;
    const int lane = tid & 31, warp = tid >> 5;
    const int tig = lane & 3, gid = lane >> 2;
    const float* Wh = W + (size_t)h * K * 64;

    float acc[8][4];
#pragma unroll
    for (int i = 0; i < 8; i++)
#pragma unroll
        for (int j = 0; j < 4; j++) acc[i][j] = 0.f;

    const int arow = warp * 16 + (lane & 15);
    const unsigned aaddr = smem_u32(&As[arow * 72 + (lane >> 4) * 8]);

#pragma unroll 1
    for (int k0 = 0; k0 < K; k0 += 64) {
        __syncthreads();
#pragma unroll
        for (int i = 0; i < 4; i++) {
            int idx = tid + i * 256;       // 0..1023
            int r = idx >> 3, c = idx & 7;
            *reinterpret_cast<uint4*>(&As[r * 72 + c * 8]) =
                *reinterpret_cast<const uint4*>(in16 + (size_t)(nb + r) * K + k0 + c * 8);
        }
#pragma unroll
        for (int i = 0; i < 4; i++) {
            int idx = tid + i * 256;
            int kk = idx >> 4, og = (idx & 15) * 4;
            float4 w4 = *reinterpret_cast<const float4*>(&Wh[(size_t)(k0 + kk) * 64 + og]);
            WT[(og + 0) * 72 + kk] = __float2half_rn(w4.x);
            WT[(og + 1) * 72 + kk] = __float2half_rn(w4.y);
            WT[(og + 2) * 72 + kk] = __float2half_rn(w4.z);
            WT[(og + 3) * 72 + kk] = __float2half_rn(w4.w);
        }
        __syncthreads();
#pragma unroll
        for (int kc = 0; kc < 4; kc++) {
            unsigned a0, a1, a2, a3;
            asm volatile("ldmatrix.sync.aligned.m8n8.x4.shared.b16 {%0,%1,%2,%3}, [%4];\n"
                         : "=r"(a0), "=r"(a1), "=r"(a2), "=r"(a3)
                         : "r"(aaddr + kc * 32));
#pragma unroll
            for (int ncp = 0; ncp < 4; ncp++) {
                int g = lane >> 3, r = lane & 7;
                int brw  = ncp * 16 + (g >> 1) * 8 + r;
                int bcol = kc * 16 + (g & 1) * 8;
                unsigned baddr = smem_u32(&WT[brw * 72 + bcol]);
                unsigned b0, b1, b2, b3;
                asm volatile("ldmatrix.sync.aligned.m8n8.x4.shared.b16 {%0,%1,%2,%3}, [%4];\n"
                             : "=r"(b0), "=r"(b1), "=r"(b2), "=r"(b3) : "r"(baddr));
                asm volatile(
                    "mma.sync.aligned.m16n8k16.row.col.f32.f16.f16.f32 "
                    "{%0,%1,%2,%3}, {%4,%5,%6,%7}, {%8,%9}, {%0,%1,%2,%3};\n"
                    : "+f"(acc[2 * ncp][0]), "+f"(acc[2 * ncp][1]),
                      "+f"(acc[2 * ncp][2]), "+f"(acc[2 * ncp][3])
                    : "r"(a0), "r"(a1), "r"(a2), "r"(a3), "r"(b0), "r"(b1));
                asm volatile(
                    "mma.sync.aligned.m16n8k16.row.col.f32.f16.f16.f32 "
                    "{%0,%1,%2,%3}, {%4,%5,%6,%7}, {%8,%9}, {%0,%1,%2,%3};\n"
                    : "+f"(acc[2 * ncp + 1][0]), "+f"(acc[2 * ncp + 1][1]),
                      "+f"(acc[2 * ncp + 1][2]), "+f"(acc[2 * ncp + 1][3])
                    : "r"(a0), "r"(a1), "r"(a2), "r"(a3), "r"(b2), "r"(b3));
            }
        }
    }

    // ---- epilogue: h16T stores + el/er + CTA max(er) -> atomicMax ----
    const int n_lo = nb + warp * 16 + gid;
    const int n_hi = n_lo + 8;
    const int hb = h * N_NODES;
    __half* hTb = h16T + ((size_t)h * 64) * N_NODES;
    const float* ah = a + h * 128;

    float pl0 = 0.f, pl1 = 0.f, pr0 = 0.f, pr1 = 0.f;
#pragma unroll
    for (int nc = 0; nc < 8; nc++) {
        const int c0 = nc * 8 + 2 * tig;
        hTb[(size_t)c0 * N_NODES + n_lo]       = __float2half_rn(acc[nc][0]);
        hTb[(size_t)(c0 + 1) * N_NODES + n_lo] = __float2half_rn(acc[nc][1]);
        hTb[(size_t)c0 * N_NODES + n_hi]       = __float2half_rn(acc[nc][2]);
        hTb[(size_t)(c0 + 1) * N_NODES + n_hi] = __float2half_rn(acc[nc][3]);
        const float al0 = ah[c0], al1 = ah[c0 + 1];
        const float ar0 = ah[64 + c0], ar1 = ah[64 + c0 + 1];
        pl0 = fmaf(acc[nc][0], al0, fmaf(acc[nc][1], al1, pl0));
        pl1 = fmaf(acc[nc][2], al0, fmaf(acc[nc][3], al1, pl1));
        pr0 = fmaf(acc[nc][0], ar0, fmaf(acc[nc][1], ar1, pr0));
        pr1 = fmaf(acc[nc][2], ar0, fmaf(acc[nc][3], ar1, pr1));
    }
#pragma unroll
    for (int o = 1; o < 4; o <<= 1) {
        pl0 += __shfl_xor_sync(0xffffffffu, pl0, o);
        pl1 += __shfl_xor_sync(0xffffffffu, pl1, o);
        pr0 += __shfl_xor_sync(0xffffffffu, pr0, o);
        pr1 += __shfl_xor_sync(0xffffffffu, pr1, o);
    }
    if (tig == 0) {
        el[hb + n_lo] = pl0; el[hb + n_hi] = pl1;
        er[hb + n_lo] = pr0; er[hb + n_hi] = pr1;
    }
    // warp max of er (pr values valid in all lanes of each 4-lane group)
    float mx = fmaxf(pr0, pr1);
#pragma unroll
    for (int o = 4; o < 32; o <<= 1) mx = fmaxf(mx, __shfl_xor_sync(0xffffffffu, mx, o));
    if (lane == 0) smax[warp] = mx;
    __syncthreads();
    if (tid == 0) {
        float mm = smax[0];
#pragma unroll
        for (int i = 1; i < 8; i++) mm = fmaxf(mm, smax[i]);
        atomicMax(&g_Cbits[h], fmap(mm));
    }
}

// ---------------- fused flash-style attention (split-m): partials = W @ h, rowsum ----------------
// Warp-M=32: 128-thread CTAs, each warp computes 32 rows (two 16-row fragment groups)
// sharing one set of B ldmatrix fragments -> B LDS traffic halves per CTA.
struct AttnSmem {
    __half hTs[2][64 * 136];    // double-buffered h tiles (cp.async), hT[o][m]  34816 B
    __half Ppk[2048], Qpk[2048];// CTA's m-range of P/Q, permuted                 8192 B
    uint2  lut[16 * 32];        // 4-bit mask index -> (m01, m89)                 4096 B
};

#define CP_ASYNC16(dst_smem, src) \
    asm volatile("cp.async.cg.shared.global [%0], [%1], 16;" :: "r"(dst_smem), "l"(src))
#define CP_COMMIT() asm volatile("cp.async.commit_group;")
#define CP_WAIT0()  asm volatile("cp.async.wait_group 0;")

#define MMA16816(acc, a0, a1, a2, a3, b0, b1) \
    asm volatile( \
        "mma.sync.aligned.m16n8k16.row.col.f32.f16.f16.f32 " \
        "{%0,%1,%2,%3}, {%4,%5,%6,%7}, {%8,%9}, {%0,%1,%2,%3};\n" \
        : "+f"((acc)[0]), "+f"((acc)[1]), "+f"((acc)[2]), "+f"((acc)[3]) \
        : "r"(a0), "r"(a1), "r"(a2), "r"(a3), "r"(b0), "r"(b1))

template<int SPLIT>
__global__ void __launch_bounds__(128, 4) k_attn(
    const __half* __restrict__ h16T,
    const float* __restrict__ elg, const float* __restrict__ erg,
    const unsigned* __restrict__ maskw,
    float* __restrict__ part, int H) {
    extern __shared__ char smem_raw[];
    AttnSmem& S = *reinterpret_cast<AttnSmem*>(smem_raw);

    constexpr int NTILES = (N_NODES / 128) / SPLIT;
    const int head = blockIdx.y;
    const int n0   = blockIdx.x * 128;
    const int tid  = threadIdx.x;
    const int lane = tid & 31, warp = tid >> 5;
    const int tig  = lane & 3, gid = lane >> 2;
    const int t2   = tig * 2;
    const int rA   = warp * 32 + gid;          // 4 rows per lane: rA, +8, +16, +24
    const int hb   = head * N_NODES;
    const int jbase = blockIdx.z * NTILES;
    const int mbase = jbase * 128;

    const float c = funmap(g_Cbits[head]);

    // stage P/Q (permuted within 16-groups: [0,1,8,9, 2,3,10,11, 4,5,12,13, 6,7,14,15])
    {
        constexpr int NM = NTILES * 128;
#pragma unroll
        for (int i = tid; i < NM; i += 128) {
            const float e_r = erg[hb + mbase + i];
            const int grp = i >> 4, ii = i & 15;
            const int pos = (ii < 8) ? ((ii >> 1) * 4 + (ii & 1))
                                     : (((ii - 8) >> 1) * 4 + 2 + (ii & 1));
            const int d = (grp << 4) + pos;
            S.Ppk[d] = __float2half_rn(expf(e_r - c));
            S.Qpk[d] = __float2half_rn(expf(0.2f * (e_r - c)));
        }
        // mask LUT: idx bits {0,1} -> m01 halves, bits {2,3} -> m89 halves
#pragma unroll
        for (int i = tid; i < 512; i += 128) {
            const int idx = i >> 5;
            unsigned m01 = ((idx & 1) ? 0x0000FFFFu : 0u) | ((idx & 2) ? 0xFFFF0000u : 0u);
            unsigned m89 = ((idx & 4) ? 0x0000FFFFu : 0u) | ((idx & 8) ? 0xFFFF0000u : 0u);
            S.lut[i] = make_uint2(m01, m89);
        }
    }
    // per-row gates (4 rows)
    __half2 g1[4], g2[4];
#pragma unroll
    for (int g = 0; g < 4; g++) {
        const float z = elg[hb + n0 + rA + 8 * g] + c;
        g1[g] = __float2half2_rn(z > 0.f ? 1.f : expf(0.8f * z));
        g2[g] = __float2half2_rn(z > 0.f ? expf(-0.8f * z) : 1.f);
    }

    float acc[2][8][4];
#pragma unroll
    for (int g = 0; g < 2; g++)
#pragma unroll
        for (int i = 0; i < 8; i++)
#pragma unroll
            for (int j = 0; j < 4; j++) acc[g][i][j] = 0.f;
    float acc_rs[2][4];
#pragma unroll
    for (int g = 0; g < 2; g++)
#pragma unroll
        for (int j = 0; j < 4; j++) acc_rs[g][j] = 0.f;

    const __half* hT = h16T + (size_t)head * 64 * N_NODES;

    auto load_tile = [&](int j, int buf) {
        const int m0 = j * 128;
#pragma unroll
        for (int i = 0; i < 8; i++) {
            int idx = tid + i * 128;
            int r = idx >> 4, cc = idx & 15;
            unsigned dst = smem_u32(&S.hTs[buf][r * 136 + cc * 8]);
            CP_ASYNC16(dst, hT + (size_t)r * N_NODES + m0 + cc * 8);
        }
        CP_COMMIT();
    };

    load_tile(jbase, 0);

#pragma unroll 1
    for (int t = 0; t < NTILES; t++) {
        const int m0 = (jbase + t) * 128;
        const int ml = m0 - mbase;
        const int buf = t & 1;

        CP_WAIT0();
        __syncthreads();
        if (t + 1 < NTILES) load_tile(jbase + t + 1, buf ^ 1);

        // adjacency words for this lane's 4 rows, this tile
        uint4 q[4];
#pragma unroll
        for (int g = 0; g < 4; g++)
            q[g] = *reinterpret_cast<const uint4*>(
                maskw + (size_t)(n0 + rA + 8 * g) * 128 + (m0 >> 5));

        const unsigned bone = 0x3C003C00u;
#pragma unroll
        for (int kc = 0; kc < 8; kc++) {
            const int stot = t2 + ((kc & 1) << 4);
            // masks for 4 rows via 4-bit LUT
            uint2 mk[4];
#pragma unroll
            for (int g = 0; g < 4; g++) {
                const unsigned w = (&q[g].x)[kc >> 1] >> stot;
                const unsigned ix = (w & 3u) | ((w >> 6) & 12u);
                mk[g] = S.lut[(ix << 5) | lane];
            }
            // one LDS.64 each: both half2 fragments of P and Q
            const int eoff = ml + kc * 16 + 4 * tig;
            const uint2 pv = *reinterpret_cast<const uint2*>(S.Ppk + eoff);
            const uint2 qv = *reinterpret_cast<const uint2*>(S.Qpk + eoff);

            unsigned fr[2][4];
#pragma unroll
            for (int g = 0; g < 2; g++) {
                fr[g][0] = h2u(__hmax2(__hmul2(g1[2*g],   u2h(pv.x)), __hmul2(g2[2*g],   u2h(qv.x)))) & mk[2*g].x;
                fr[g][1] = h2u(__hmax2(__hmul2(g1[2*g+1], u2h(pv.x)), __hmul2(g2[2*g+1], u2h(qv.x)))) & mk[2*g+1].x;
                fr[g][2] = h2u(__hmax2(__hmul2(g1[2*g],   u2h(pv.y)), __hmul2(g2[2*g],   u2h(qv.y)))) & mk[2*g].y;
                fr[g][3] = h2u(__hmax2(__hmul2(g1[2*g+1], u2h(pv.y)), __hmul2(g2[2*g+1], u2h(qv.y)))) & mk[2*g+1].y;
                MMA16816(acc_rs[g], fr[g][0], fr[g][1], fr[g][2], fr[g][3], bone, bone);
            }
#pragma unroll
            for (int ncp = 0; ncp < 4; ncp++) {
                int gg = lane >> 3, r = lane & 7;
                int brw  = ncp * 16 + (gg >> 1) * 8 + r;
                int bcol = kc * 16 + (gg & 1) * 8;
                unsigned baddr = smem_u32(&S.hTs[buf][brw * 136 + bcol]);
                unsigned b0, b1, b2, b3;
                asm volatile("ldmatrix.sync.aligned.m8n8.x4.shared.b16 {%0,%1,%2,%3}, [%4];\n"
                             : "=r"(b0), "=r"(b1), "=r"(b2), "=r"(b3) : "r"(baddr));
#pragma unroll
                for (int g = 0; g < 2; g++) {
                    MMA16816(acc[g][2 * ncp],     fr[g][0], fr[g][1], fr[g][2], fr[g][3], b0, b1);
                    MMA16816(acc[g][2 * ncp + 1], fr[g][0], fr[g][1], fr[g][2], fr[g][3], b2, b3);
                }
            }
        }
    }

    // ---- write partials (numerator + rowsum) for 4 rows ----
    float* pbase = part + (((size_t)blockIdx.z * H + head) * N_NODES + n0) * 68;
#pragma unroll
    for (int g = 0; g < 2; g++) {
        const int r0 = rA + 16 * g, r1 = r0 + 8;
#pragma unroll
        for (int nc = 0; nc < 8; nc++) {
            int col = nc * 8 + t2;
            *reinterpret_cast<float2*>(pbase + (size_t)r0 * 68 + col) = make_float2(acc[g][nc][0], acc[g][nc][1]);
            *reinterpret_cast<float2*>(pbase + (size_t)r1 * 68 + col) = make_float2(acc[g][nc][2], acc[g][nc][3]);
        }
        if (tig == 0) {
            pbase[(size_t)r0 * 68 + 64] = acc_rs[g][0];
            pbase[(size_t)r1 * 68 + 64] = acc_rs[g][2];
        }
    }
}

// ---------------- combine split-m partials: divide + optional ELU; fp16 or fp32 out ----------------
// Also resets g_Cbits for the NEXT layer's feature kernel.
template<bool HALF_OUT>
__global__ void k_combine(const float* __restrict__ part, float* __restrict__ fout,
                          __half* __restrict__ hout,
                          int H, int SPLIT, int outStride, int applyElu) {
    if (blockIdx.x == 0 && threadIdx.x < MAXH) g_Cbits[threadIdx.x] = 0u;
    const int idx = blockIdx.x * 256 + threadIdx.x;    // over H*N*64
    const int o = idx & 63, n = (idx >> 6) & (N_NODES - 1), head = idx >> 18;
    float s = 0.f, r = 0.f;
    for (int z = 0; z < SPLIT; z++) {
        const float* pb = part + (((size_t)z * H + head) * N_NODES + n) * 68;
        s += pb[o];
        r += pb[64];
    }
    float v = s / r;
    if (applyElu) v = v > 0.f ? v : expm1f(v);
    if (HALF_OUT) hout[(size_t)n * outStride + head * 64 + o] = __float2half_rn(v);
    else          fout[(size_t)n * outStride + head * 64 + o] = v;
}

// ---------------- host orchestration ----------------
struct Scratch {
    unsigned* maskw; __half* h16T;
    float *el, *er, *part;
    __half *x16, *bufA, *bufB;
};

static void run_layer(const __half* in16, int K, const float* W, const float* a, int H,
                      float* foutp, __half* houtp, int outStride, int applyElu,
                      const Scratch& s) {
    if (K == 128) k_feat_tc<128><<<dim3(N_NODES / 128, H), 256>>>(in16, W, a, s.h16T, s.el, s.er);
    else          k_feat_tc<256><<<dim3(N_NODES / 128, H), 256>>>(in16, W, a, s.h16T, s.el, s.er);
    if (H == 4) {
        k_attn<4><<<dim3(N_NODES / 128, H, 4), 128, sizeof(AttnSmem)>>>(
            s.h16T, s.el, s.er, s.maskw, s.part, H);
        if (houtp) k_combine<true ><<<H * N_NODES * 64 / 256, 256>>>(s.part, foutp, houtp, H, 4, outStride, applyElu);
        else       k_combine<false><<<H * N_NODES * 64 / 256, 256>>>(s.part, foutp, houtp, H, 4, outStride, applyElu);
    } else {
        k_attn<8><<<dim3(N_NODES / 128, H, 8), 128, sizeof(AttnSmem)>>>(
            s.h16T, s.el, s.er, s.maskw, s.part, H);
        if (houtp) k_combine<true ><<<H * N_NODES * 64 / 256, 256>>>(s.part, foutp, houtp, H, 8, outStride, applyElu);
        else       k_combine<false><<<H * N_NODES * 64 / 256, 256>>>(s.part, foutp, houtp, H, 8, outStride, applyElu);
    }
}

extern "C" void kernel_launch(void* const* d_in, const int* in_sizes, int n_in,
                              void* d_out, int out_size) {
    (void)in_sizes; (void)n_in; (void)out_size;
    const float* x  = (const float*)d_in[0];
    const int*   adj = (const int*)d_in[1];
    const float* W0 = (const float*)d_in[2];
    const float* a0 = (const float*)d_in[3];
    const float* W1 = (const float*)d_in[4];
    const float* a1 = (const float*)d_in[5];
    const float* W2 = (const float*)d_in[6];
    const float* a2 = (const float*)d_in[7];

    cudaFuncSetAttribute(k_attn<4>, cudaFuncAttributeMaxDynamicSharedMemorySize,
                         (int)sizeof(AttnSmem));
    cudaFuncSetAttribute(k_attn<8>, cudaFuncAttributeMaxDynamicSharedMemorySize,
                         (int)sizeof(AttnSmem));

    Scratch s;
    void* p;
    cudaGetSymbolAddress(&p, g_maskw); s.maskw = (unsigned*)p;
    cudaGetSymbolAddress(&p, g_h16T);  s.h16T  = (__half*)p;
    cudaGetSymbolAddress(&p, g_el);    s.el    = (float*)p;
    cudaGetSymbolAddress(&p, g_er);    s.er    = (float*)p;
    cudaGetSymbolAddress(&p, g_part);  s.part  = (float*)p;
    cudaGetSymbolAddress(&p, g_x16);   s.x16   = (__half*)p;
    cudaGetSymbolAddress(&p, g_bufA);  s.bufA  = (__half*)p;
    cudaGetSymbolAddress(&p, g_bufB);  s.bufB  = (__half*)p;

    k_mask<<<N_NODES, 1024>>>(adj, s.maskw);
    k_x2h<<<(N_NODES * 128 / 4 + 255) / 256, 256>>>(x, s.x16, N_NODES * 128 / 4);

    run_layer(s.x16,  128, W0, a0, 4, nullptr,        s.bufA, 256, 1, s);
    run_layer(s.bufA, 256, W1, a1, 4, nullptr,        s.bufB, 256, 1, s);
    run_layer(s.bufB, 256, W2, a2, 1, (float*)d_out,  nullptr, 64, 0, s);
}